// round 1
// baseline (speedup 1.0000x reference)
#include <cuda_runtime.h>
#include <math.h>

// Problem constants: RetentionHead  B=4, T=4096, C=1024, H=128
#define BN 4
#define TN 4096
#define CN 1024
#define HN 128
#define LN 128                 // chunk length
#define NCN (TN / LN)          // 32 chunks per batch
#define MN (BN * TN)           // 16384 rows
#define GAMMA 0.96875f
#define SCALE 0.03125f         // C^-0.5 = 1/32

// ---------------- scratch (device globals; no allocation allowed) ----------
__device__ float g_q[MN * HN];             // 8 MB
__device__ float g_k[MN * HN];             // 8 MB
__device__ float g_v[MN * HN];             // 8 MB
__device__ float g_A[BN * NCN * HN * HN];  // per-chunk decayed KV outer products, 8 MB
__device__ float g_S[BN * NCN * HN * HN];  // prefix states, 8 MB

// ===========================================================================
// Kernel 1: projections  q|k|v = x @ W   (M=16384, K=1024, N=128)
// grid (M/128, 3), 256 threads, 128x128 tile, BK=16, 8x8 microtile.
// q is pre-scaled by C^-0.5.
// ===========================================================================
__global__ __launch_bounds__(256) void proj_kernel(
    const float* __restrict__ x,
    const float* __restrict__ Wq,
    const float* __restrict__ Wk,
    const float* __restrict__ Wv)
{
    __shared__ float As[16][132];   // x tile, transposed: As[k][m]
    __shared__ float Bs[16][132];   // W tile, natural:   Bs[k][n]

    const int m0    = blockIdx.x * 128;
    const int which = blockIdx.y;
    const float* __restrict__ W = (which == 0) ? Wq : (which == 1) ? Wk : Wv;
    float* __restrict__ out     = (which == 0) ? g_q : (which == 1) ? g_k : g_v;
    const float postscale = (which == 0) ? SCALE : 1.0f;

    const int tid = threadIdx.x;
    const int tr  = tid >> 4;   // 0..15
    const int tc  = tid & 15;   // 0..15

    float acc[8][8];
#pragma unroll
    for (int i = 0; i < 8; ++i)
#pragma unroll
        for (int j = 0; j < 8; ++j) acc[i][j] = 0.0f;

    for (int kt = 0; kt < CN / 16; ++kt) {
        // x tile: rows m0..m0+127, cols kt*16..+15  -> transposed store
#pragma unroll
        for (int r = 0; r < 2; ++r) {
            int id  = tid + 256 * r;       // 0..511 float4s
            int row = id >> 2;
            int c4  = id & 3;
            float4 xv = *reinterpret_cast<const float4*>(
                &x[(size_t)(m0 + row) * CN + kt * 16 + c4 * 4]);
            As[c4 * 4 + 0][row] = xv.x;
            As[c4 * 4 + 1][row] = xv.y;
            As[c4 * 4 + 2][row] = xv.z;
            As[c4 * 4 + 3][row] = xv.w;
        }
        // W tile [16][128], natural
#pragma unroll
        for (int r = 0; r < 2; ++r) {
            int id  = tid + 256 * r;
            int row = id >> 5;
            int c4  = id & 31;
            *reinterpret_cast<float4*>(&Bs[row][c4 * 4]) =
                *reinterpret_cast<const float4*>(&W[(size_t)(kt * 16 + row) * HN + c4 * 4]);
        }
        __syncthreads();
#pragma unroll
        for (int kk = 0; kk < 16; ++kk) {
            float4 a0 = *reinterpret_cast<const float4*>(&As[kk][tr * 8]);
            float4 a1 = *reinterpret_cast<const float4*>(&As[kk][tr * 8 + 4]);
            float4 b0 = *reinterpret_cast<const float4*>(&Bs[kk][tc * 8]);
            float4 b1 = *reinterpret_cast<const float4*>(&Bs[kk][tc * 8 + 4]);
            float a[8] = {a0.x, a0.y, a0.z, a0.w, a1.x, a1.y, a1.z, a1.w};
            float b[8] = {b0.x, b0.y, b0.z, b0.w, b1.x, b1.y, b1.z, b1.w};
#pragma unroll
            for (int i = 0; i < 8; ++i)
#pragma unroll
                for (int j = 0; j < 8; ++j) acc[i][j] = fmaf(a[i], b[j], acc[i][j]);
        }
        __syncthreads();
    }
#pragma unroll
    for (int i = 0; i < 8; ++i) {
        int row = m0 + tr * 8 + i;
#pragma unroll
        for (int j = 0; j < 8; j += 4) {
            float4 v;
            v.x = acc[i][j + 0] * postscale;
            v.y = acc[i][j + 1] * postscale;
            v.z = acc[i][j + 2] * postscale;
            v.w = acc[i][j + 3] * postscale;
            *reinterpret_cast<float4*>(&out[(size_t)row * HN + tc * 8 + j]) = v;
        }
    }
}

// ===========================================================================
// Kernel 2: per-chunk decayed outer product A_c[hk][hv] = sum_j g^(L-j) k[j,hk] v[j,hv]
// grid (NC, B), 256 threads. 128x128x128.
// ===========================================================================
__global__ __launch_bounds__(256) void chunkkv_kernel()
{
    __shared__ float Ks[16][132];   // (w*k)[j][hk]  natural
    __shared__ float Vs[16][132];   // v[j][hv]      natural

    const int c = blockIdx.x;
    const int b = blockIdx.y;
    const float* __restrict__ kp = g_k + (size_t)(b * TN + c * LN) * HN;
    const float* __restrict__ vp = g_v + (size_t)(b * TN + c * LN) * HN;
    float* __restrict__ ap = g_A + (size_t)(b * NCN + c) * HN * HN;

    const int tid = threadIdx.x;
    const int tr  = tid >> 4;
    const int tc  = tid & 15;

    float acc[8][8];
#pragma unroll
    for (int i = 0; i < 8; ++i)
#pragma unroll
        for (int j = 0; j < 8; ++j) acc[i][j] = 0.0f;

    for (int jt = 0; jt < 8; ++jt) {
#pragma unroll
        for (int r = 0; r < 2; ++r) {
            int id  = tid + 256 * r;
            int row = id >> 5;          // 0..15 (local j)
            int c4  = id & 31;
            int j   = jt * 16 + row;
            float w = powf(GAMMA, (float)(LN - j));  // g^(L-j), <= 1
            float4 kv = *reinterpret_cast<const float4*>(&kp[(size_t)j * HN + c4 * 4]);
            float4 vv = *reinterpret_cast<const float4*>(&vp[(size_t)j * HN + c4 * 4]);
            kv.x *= w; kv.y *= w; kv.z *= w; kv.w *= w;
            *reinterpret_cast<float4*>(&Ks[row][c4 * 4]) = kv;
            *reinterpret_cast<float4*>(&Vs[row][c4 * 4]) = vv;
        }
        __syncthreads();
#pragma unroll
        for (int kk = 0; kk < 16; ++kk) {
            float4 a0 = *reinterpret_cast<const float4*>(&Ks[kk][tr * 8]);
            float4 a1 = *reinterpret_cast<const float4*>(&Ks[kk][tr * 8 + 4]);
            float4 b0 = *reinterpret_cast<const float4*>(&Vs[kk][tc * 8]);
            float4 b1 = *reinterpret_cast<const float4*>(&Vs[kk][tc * 8 + 4]);
            float a[8] = {a0.x, a0.y, a0.z, a0.w, a1.x, a1.y, a1.z, a1.w};
            float b[8] = {b0.x, b0.y, b0.z, b0.w, b1.x, b1.y, b1.z, b1.w};
#pragma unroll
            for (int i = 0; i < 8; ++i)
#pragma unroll
                for (int j = 0; j < 8; ++j) acc[i][j] = fmaf(a[i], b[j], acc[i][j]);
        }
        __syncthreads();
    }
#pragma unroll
    for (int i = 0; i < 8; ++i)
#pragma unroll
        for (int j = 0; j < 8; j += 4) {
            float4 v = {acc[i][j], acc[i][j + 1], acc[i][j + 2], acc[i][j + 3]};
            *reinterpret_cast<float4*>(&ap[(size_t)(tr * 8 + i) * HN + tc * 8 + j]) = v;
        }
}

// ===========================================================================
// Kernel 3: sequential prefix scan of states per (b, hk, hv) element.
// S_0 = 0; S_{c+1} = g^L * S_c + A_c.  65536 threads, 32 steps each.
// ===========================================================================
__global__ void scan_kernel()
{
    int idx = blockIdx.x * blockDim.x + threadIdx.x;
    if (idx >= BN * HN * HN) return;
    int b = idx / (HN * HN);
    int e = idx % (HN * HN);
    const float gL = powf(GAMMA, (float)LN);
    float S = 0.0f;
    for (int c = 0; c < NCN; ++c) {
        size_t off = (size_t)(b * NCN + c) * HN * HN + e;
        g_S[off] = S;
        S = fmaf(S, gL, g_A[off]);
    }
}

// ===========================================================================
// Kernel 4: per-chunk output.
//   P[i][j] = (q_s[i] . k[j]) * g^(i-j) (causal)       [q_s already has C^-0.5]
//   out     = P @ V  +  (g^i * q_s) @ S_c
// grid (NC, B), 256 threads. P kept in registers, consumed in 16-wide stripes.
// ===========================================================================
__global__ __launch_bounds__(256) void out_kernel(float* __restrict__ out)
{
    __shared__ float Ast[16][132];   // A-operand staging (transposed tiles / P stripes)
    __shared__ float Bst[16][132];   // B-operand staging (natural tiles)
    __shared__ float gpow[129];      // gamma^0 .. gamma^128

    const int c = blockIdx.x;
    const int b = blockIdx.y;
    const size_t rowbase = (size_t)(b * TN + c * LN);
    const float* __restrict__ qp = g_q + rowbase * HN;
    const float* __restrict__ kp = g_k + rowbase * HN;
    const float* __restrict__ vp = g_v + rowbase * HN;
    const float* __restrict__ sp = g_S + (size_t)(b * NCN + c) * HN * HN;

    const int tid = threadIdx.x;
    const int tr  = tid >> 4;
    const int tc  = tid & 15;

    if (tid < 129) gpow[tid] = powf(GAMMA, (float)tid);

    // ---------------- phase 1: P = q_s @ k^T ------------------------------
    float pAcc[8][8];
#pragma unroll
    for (int i = 0; i < 8; ++i)
#pragma unroll
        for (int j = 0; j < 8; ++j) pAcc[i][j] = 0.0f;

    for (int ht = 0; ht < 8; ++ht) {
        // q tile rows i=0..127, cols hk0..hk0+15 -> Ast[kk][i]
#pragma unroll
        for (int r = 0; r < 2; ++r) {
            int id  = tid + 256 * r;
            int row = id >> 2;
            int c4  = id & 3;
            float4 qv = *reinterpret_cast<const float4*>(
                &qp[(size_t)row * HN + ht * 16 + c4 * 4]);
            Ast[c4 * 4 + 0][row] = qv.x;
            Ast[c4 * 4 + 1][row] = qv.y;
            Ast[c4 * 4 + 2][row] = qv.z;
            Ast[c4 * 4 + 3][row] = qv.w;
        }
        // k tile rows j=0..127 -> Bst[kk][j] (transposed too)
#pragma unroll
        for (int r = 0; r < 2; ++r) {
            int id  = tid + 256 * r;
            int row = id >> 2;
            int c4  = id & 3;
            float4 kv = *reinterpret_cast<const float4*>(
                &kp[(size_t)row * HN + ht * 16 + c4 * 4]);
            Bst[c4 * 4 + 0][row] = kv.x;
            Bst[c4 * 4 + 1][row] = kv.y;
            Bst[c4 * 4 + 2][row] = kv.z;
            Bst[c4 * 4 + 3][row] = kv.w;
        }
        __syncthreads();
#pragma unroll
        for (int kk = 0; kk < 16; ++kk) {
            float4 a0 = *reinterpret_cast<const float4*>(&Ast[kk][tr * 8]);
            float4 a1 = *reinterpret_cast<const float4*>(&Ast[kk][tr * 8 + 4]);
            float4 b0 = *reinterpret_cast<const float4*>(&Bst[kk][tc * 8]);
            float4 b1 = *reinterpret_cast<const float4*>(&Bst[kk][tc * 8 + 4]);
            float a[8] = {a0.x, a0.y, a0.z, a0.w, a1.x, a1.y, a1.z, a1.w};
            float bb[8] = {b0.x, b0.y, b0.z, b0.w, b1.x, b1.y, b1.z, b1.w};
#pragma unroll
            for (int i = 0; i < 8; ++i)
#pragma unroll
                for (int j = 0; j < 8; ++j) pAcc[i][j] = fmaf(a[i], bb[j], pAcc[i][j]);
        }
        __syncthreads();
    }

    // decay mask: P[i][j] *= g^(i-j) if i>=j else 0
#pragma unroll
    for (int ii = 0; ii < 8; ++ii) {
        int i = tr * 8 + ii;
#pragma unroll
        for (int jj = 0; jj < 8; ++jj) {
            int j = tc * 8 + jj;
            int d = i - j;
            pAcc[ii][jj] = (d >= 0) ? pAcc[ii][jj] * gpow[d] : 0.0f;
        }
    }

    // ---------------- phase 2a: out = P @ V -------------------------------
    float oAcc[8][8];
#pragma unroll
    for (int i = 0; i < 8; ++i)
#pragma unroll
        for (int j = 0; j < 8; ++j) oAcc[i][j] = 0.0f;

    for (int jt = 0; jt < 8; ++jt) {
        // owners of columns j in [jt*16, jt*16+16) write transposed stripe Ast[jl][i]
        if ((tc >> 1) == jt) {
            int jbase = (tc & 1) * 8;
#pragma unroll
            for (int jj = 0; jj < 8; ++jj)
#pragma unroll
                for (int ii = 0; ii < 8; ++ii)
                    Ast[jbase + jj][tr * 8 + ii] = pAcc[ii][jj];
        }
        // V tile [16][128] natural
#pragma unroll
        for (int r = 0; r < 2; ++r) {
            int id  = tid + 256 * r;
            int row = id >> 5;
            int c4  = id & 31;
            *reinterpret_cast<float4*>(&Bst[row][c4 * 4]) =
                *reinterpret_cast<const float4*>(&vp[(size_t)(jt * 16 + row) * HN + c4 * 4]);
        }
        __syncthreads();
#pragma unroll
        for (int kk = 0; kk < 16; ++kk) {
            float4 a0 = *reinterpret_cast<const float4*>(&Ast[kk][tr * 8]);
            float4 a1 = *reinterpret_cast<const float4*>(&Ast[kk][tr * 8 + 4]);
            float4 b0 = *reinterpret_cast<const float4*>(&Bst[kk][tc * 8]);
            float4 b1 = *reinterpret_cast<const float4*>(&Bst[kk][tc * 8 + 4]);
            float a[8] = {a0.x, a0.y, a0.z, a0.w, a1.x, a1.y, a1.z, a1.w};
            float bb[8] = {b0.x, b0.y, b0.z, b0.w, b1.x, b1.y, b1.z, b1.w};
#pragma unroll
            for (int i = 0; i < 8; ++i)
#pragma unroll
                for (int j = 0; j < 8; ++j) oAcc[i][j] = fmaf(a[i], bb[j], oAcc[i][j]);
        }
        __syncthreads();
    }

    // ---------------- phase 2b: out += (g^i * q_s) @ S_c ------------------
    for (int ht = 0; ht < 8; ++ht) {
        // q tile transposed, scaled by g^i
#pragma unroll
        for (int r = 0; r < 2; ++r) {
            int id  = tid + 256 * r;
            int row = id >> 2;
            int c4  = id & 3;
            float g = gpow[row];
            float4 qv = *reinterpret_cast<const float4*>(
                &qp[(size_t)row * HN + ht * 16 + c4 * 4]);
            Ast[c4 * 4 + 0][row] = qv.x * g;
            Ast[c4 * 4 + 1][row] = qv.y * g;
            Ast[c4 * 4 + 2][row] = qv.z * g;
            Ast[c4 * 4 + 3][row] = qv.w * g;
        }
        // S tile [16][128] natural (rows hk, cols hv)
#pragma unroll
        for (int r = 0; r < 2; ++r) {
            int id  = tid + 256 * r;
            int row = id >> 5;
            int c4  = id & 31;
            *reinterpret_cast<float4*>(&Bst[row][c4 * 4]) =
                *reinterpret_cast<const float4*>(&sp[(size_t)(ht * 16 + row) * HN + c4 * 4]);
        }
        __syncthreads();
#pragma unroll
        for (int kk = 0; kk < 16; ++kk) {
            float4 a0 = *reinterpret_cast<const float4*>(&Ast[kk][tr * 8]);
            float4 a1 = *reinterpret_cast<const float4*>(&Ast[kk][tr * 8 + 4]);
            float4 b0 = *reinterpret_cast<const float4*>(&Bst[kk][tc * 8]);
            float4 b1 = *reinterpret_cast<const float4*>(&Bst[kk][tc * 8 + 4]);
            float a[8] = {a0.x, a0.y, a0.z, a0.w, a1.x, a1.y, a1.z, a1.w};
            float bb[8] = {b0.x, b0.y, b0.z, b0.w, b1.x, b1.y, b1.z, b1.w};
#pragma unroll
            for (int i = 0; i < 8; ++i)
#pragma unroll
                for (int j = 0; j < 8; ++j) oAcc[i][j] = fmaf(a[i], bb[j], oAcc[i][j]);
        }
        __syncthreads();
    }

    // store out rows
#pragma unroll
    for (int i = 0; i < 8; ++i) {
        size_t row = rowbase + tr * 8 + i;
#pragma unroll
        for (int j = 0; j < 8; j += 4) {
            float4 v = {oAcc[i][j], oAcc[i][j + 1], oAcc[i][j + 2], oAcc[i][j + 3]};
            *reinterpret_cast<float4*>(&out[row * HN + tc * 8 + j]) = v;
        }
    }
}

// ===========================================================================
extern "C" void kernel_launch(void* const* d_in, const int* in_sizes, int n_in,
                              void* d_out, int out_size)
{
    const float* x  = (const float*)d_in[0];
    const float* Wq = (const float*)d_in[1];
    const float* Wk = (const float*)d_in[2];
    const float* Wv = (const float*)d_in[3];
    float* out = (float*)d_out;

    proj_kernel<<<dim3(MN / 128, 3), 256>>>(x, Wq, Wk, Wv);
    chunkkv_kernel<<<dim3(NCN, BN), 256>>>();
    scan_kernel<<<(BN * HN * HN + 255) / 256, 256>>>();
    out_kernel<<<dim3(NCN, BN), 256>>>(out);
}

// round 2
// speedup vs baseline: 1.3135x; 1.3135x over previous
#include <cuda_runtime.h>
#include <math.h>

// Problem constants: RetentionHead  B=4, T=4096, C=1024, H=128
#define BN 4
#define TN 4096
#define CN 1024
#define HN 128
#define LN 128                 // chunk length
#define NCN (TN / LN)          // 32 chunks per batch
#define MN (BN * TN)           // 16384 rows
#define GAMMA 0.96875f
#define SCALE 0.03125f         // C^-0.5 = 1/32

typedef unsigned long long ull;

// ---------------- packed f32x2 helpers (Blackwell FFMA2 path) --------------
__device__ __forceinline__ ull pack2(float lo, float hi) {
    ull r;
    asm("mov.b64 %0, {%1, %2};" : "=l"(r) : "f"(lo), "f"(hi));
    return r;
}
__device__ __forceinline__ float2 unpack2(ull v) {
    float2 f;
    asm("mov.b64 {%0, %1}, %2;" : "=f"(f.x), "=f"(f.y) : "l"(v));
    return f;
}
__device__ __forceinline__ void fma2(ull& d, ull a, ull b) {
    asm("fma.rn.f32x2 %0, %1, %2, %3;" : "=l"(d) : "l"(a), "l"(b), "l"(d));
}
__device__ __forceinline__ void mul2(ull& d, ull a, ull b) {
    asm("mul.rn.f32x2 %0, %1, %2;" : "=l"(d) : "l"(a), "l"(b));
}

// ---------------- scratch (device globals; no allocation allowed) ----------
__device__ float g_q[MN * HN];             // 8 MB
__device__ float g_k[MN * HN];             // 8 MB
__device__ float g_v[MN * HN];             // 8 MB
__device__ float g_A[BN * NCN * HN * HN];  // per-chunk decayed KV outer products
__device__ float g_S[BN * NCN * HN * HN];  // prefix states

// ===========================================================================
// Kernel 1: projections  q|k|v = x @ W   (M=16384, K=1024, N=128)
// grid (M/128, 3), 256 threads, 128x128 tile, BK=16, 8x8 microtile via FFMA2.
// Register prefetch double-buffering; 2 CTAs/SM.
// ===========================================================================
__global__ __launch_bounds__(256, 2) void proj_kernel(
    const float* __restrict__ x,
    const float* __restrict__ Wq,
    const float* __restrict__ Wk,
    const float* __restrict__ Wv)
{
    __shared__ float As[16][132];   // x tile, transposed: As[k][m]
    __shared__ float Bs[16][132];   // W tile, natural:   Bs[k][n]

    const int m0    = blockIdx.x * 128;
    const int which = blockIdx.y;
    const float* __restrict__ W = (which == 0) ? Wq : (which == 1) ? Wk : Wv;
    float* __restrict__ out     = (which == 0) ? g_q : (which == 1) ? g_k : g_v;
    const float postscale = (which == 0) ? SCALE : 1.0f;

    const int tid = threadIdx.x;
    const int tr  = tid >> 4;   // 0..15
    const int tc  = tid & 15;   // 0..15

    // per-thread load coordinates
    const int xrow0 = tid >> 2;          // x tile: id = tid (+256)
    const int xc4   = tid & 3;
    const int wrow0 = tid >> 5;          // W tile
    const int wc4   = tid & 31;

    ull acc[8][4];
#pragma unroll
    for (int i = 0; i < 8; ++i)
#pragma unroll
        for (int j = 0; j < 4; ++j) acc[i][j] = 0ull;

    // prologue: load kt = 0 straight into smem
    {
#pragma unroll
        for (int r = 0; r < 2; ++r) {
            int row = xrow0 + 64 * r;
            float4 xv = *reinterpret_cast<const float4*>(
                &x[(size_t)(m0 + row) * CN + xc4 * 4]);
            As[xc4 * 4 + 0][row] = xv.x;
            As[xc4 * 4 + 1][row] = xv.y;
            As[xc4 * 4 + 2][row] = xv.z;
            As[xc4 * 4 + 3][row] = xv.w;
        }
#pragma unroll
        for (int r = 0; r < 2; ++r) {
            int row = wrow0 + 8 * r;
            *reinterpret_cast<float4*>(&Bs[row][wc4 * 4]) =
                *reinterpret_cast<const float4*>(&W[(size_t)row * HN + wc4 * 4]);
        }
    }
    __syncthreads();

    for (int kt = 0; kt < CN / 16; ++kt) {
        float4 px[2], pw[2];
        if (kt < CN / 16 - 1) {
            int k0 = (kt + 1) * 16;
#pragma unroll
            for (int r = 0; r < 2; ++r) {
                int row = xrow0 + 64 * r;
                px[r] = *reinterpret_cast<const float4*>(
                    &x[(size_t)(m0 + row) * CN + k0 + xc4 * 4]);
            }
#pragma unroll
            for (int r = 0; r < 2; ++r) {
                int row = wrow0 + 8 * r;
                pw[r] = *reinterpret_cast<const float4*>(
                    &W[(size_t)(k0 + row) * HN + wc4 * 4]);
            }
        }
#pragma unroll
        for (int kk = 0; kk < 16; ++kk) {
            float4 a0 = *reinterpret_cast<const float4*>(&As[kk][tr * 8]);
            float4 a1 = *reinterpret_cast<const float4*>(&As[kk][tr * 8 + 4]);
            const ull* bq = reinterpret_cast<const ull*>(&Bs[kk][tc * 8]);
            ull b0 = bq[0], b1 = bq[1], b2 = bq[2], b3 = bq[3];
            ull ad[8];
            ad[0] = pack2(a0.x, a0.x); ad[1] = pack2(a0.y, a0.y);
            ad[2] = pack2(a0.z, a0.z); ad[3] = pack2(a0.w, a0.w);
            ad[4] = pack2(a1.x, a1.x); ad[5] = pack2(a1.y, a1.y);
            ad[6] = pack2(a1.z, a1.z); ad[7] = pack2(a1.w, a1.w);
#pragma unroll
            for (int i = 0; i < 8; ++i) {
                fma2(acc[i][0], ad[i], b0);
                fma2(acc[i][1], ad[i], b1);
                fma2(acc[i][2], ad[i], b2);
                fma2(acc[i][3], ad[i], b3);
            }
        }
        __syncthreads();
        if (kt < CN / 16 - 1) {
#pragma unroll
            for (int r = 0; r < 2; ++r) {
                int row = xrow0 + 64 * r;
                As[xc4 * 4 + 0][row] = px[r].x;
                As[xc4 * 4 + 1][row] = px[r].y;
                As[xc4 * 4 + 2][row] = px[r].z;
                As[xc4 * 4 + 3][row] = px[r].w;
            }
#pragma unroll
            for (int r = 0; r < 2; ++r) {
                int row = wrow0 + 8 * r;
                *reinterpret_cast<float4*>(&Bs[row][wc4 * 4]) = pw[r];
            }
            __syncthreads();
        }
    }
#pragma unroll
    for (int i = 0; i < 8; ++i) {
        int row = m0 + tr * 8 + i;
        float2 p0 = unpack2(acc[i][0]), p1 = unpack2(acc[i][1]);
        float2 p2 = unpack2(acc[i][2]), p3 = unpack2(acc[i][3]);
        float4 v0 = {p0.x * postscale, p0.y * postscale, p1.x * postscale, p1.y * postscale};
        float4 v1 = {p2.x * postscale, p2.y * postscale, p3.x * postscale, p3.y * postscale};
        *reinterpret_cast<float4*>(&out[(size_t)row * HN + tc * 8])     = v0;
        *reinterpret_cast<float4*>(&out[(size_t)row * HN + tc * 8 + 4]) = v1;
    }
}

// ===========================================================================
// Kernel 2: A_c[hk][hv] = sum_j g^(L-j) k[j,hk] v[j,hv]
// grid (NC, B, 2): z = hv half. 128 threads, 128x64 per block, 8x8 micro.
// ===========================================================================
__global__ __launch_bounds__(128) void chunkkv_kernel()
{
    __shared__ float Ks[16][132];   // (w*k)[j][hk]  natural, full 128 hk
    __shared__ float Vs[16][68];    // v[j][hv-half]
    __shared__ float gp[132];       // gamma^0..gamma^128

    const int c    = blockIdx.x;
    const int b    = blockIdx.y;
    const int half = blockIdx.z;
    const float* __restrict__ kp = g_k + (size_t)(b * TN + c * LN) * HN;
    const float* __restrict__ vp = g_v + (size_t)(b * TN + c * LN) * HN;
    float* __restrict__ ap = g_A + (size_t)(b * NCN + c) * HN * HN;

    const int tid = threadIdx.x;
    const int tr  = tid >> 3;   // 0..15 -> hk rows tr*8..
    const int tc  = tid & 7;    // 0..7  -> hv cols half*64 + tc*8..

    gp[tid] = powf(GAMMA, (float)tid);
    if (tid == 0) gp[128] = powf(GAMMA, 128.0f);
    __syncthreads();

    ull acc[8][4];
#pragma unroll
    for (int i = 0; i < 8; ++i)
#pragma unroll
        for (int j = 0; j < 4; ++j) acc[i][j] = 0ull;

    for (int jt = 0; jt < 8; ++jt) {
        // K stripe [16 j][128 hk], scaled by g^(L-j)
#pragma unroll
        for (int r = 0; r < 4; ++r) {
            int id  = tid + 128 * r;
            int row = id >> 5;          // 0..15 local j
            int c4  = id & 31;
            int j   = jt * 16 + row;
            float w = gp[LN - j];
            float4 kv = *reinterpret_cast<const float4*>(&kp[(size_t)j * HN + c4 * 4]);
            kv.x *= w; kv.y *= w; kv.z *= w; kv.w *= w;
            *reinterpret_cast<float4*>(&Ks[row][c4 * 4]) = kv;
        }
        // V stripe [16 j][64 hv-half]
#pragma unroll
        for (int r = 0; r < 2; ++r) {
            int id  = tid + 128 * r;
            int row = id >> 4;          // 0..15
            int c4  = id & 15;
            int j   = jt * 16 + row;
            *reinterpret_cast<float4*>(&Vs[row][c4 * 4]) =
                *reinterpret_cast<const float4*>(&vp[(size_t)j * HN + half * 64 + c4 * 4]);
        }
        __syncthreads();
#pragma unroll
        for (int kk = 0; kk < 16; ++kk) {
            float4 a0 = *reinterpret_cast<const float4*>(&Ks[kk][tr * 8]);
            float4 a1 = *reinterpret_cast<const float4*>(&Ks[kk][tr * 8 + 4]);
            const ull* bq = reinterpret_cast<const ull*>(&Vs[kk][tc * 8]);
            ull b0 = bq[0], b1 = bq[1], b2 = bq[2], b3 = bq[3];
            ull ad[8];
            ad[0] = pack2(a0.x, a0.x); ad[1] = pack2(a0.y, a0.y);
            ad[2] = pack2(a0.z, a0.z); ad[3] = pack2(a0.w, a0.w);
            ad[4] = pack2(a1.x, a1.x); ad[5] = pack2(a1.y, a1.y);
            ad[6] = pack2(a1.z, a1.z); ad[7] = pack2(a1.w, a1.w);
#pragma unroll
            for (int i = 0; i < 8; ++i) {
                fma2(acc[i][0], ad[i], b0);
                fma2(acc[i][1], ad[i], b1);
                fma2(acc[i][2], ad[i], b2);
                fma2(acc[i][3], ad[i], b3);
            }
        }
        __syncthreads();
    }
#pragma unroll
    for (int i = 0; i < 8; ++i) {
        int row = tr * 8 + i;
        float2 p0 = unpack2(acc[i][0]), p1 = unpack2(acc[i][1]);
        float2 p2 = unpack2(acc[i][2]), p3 = unpack2(acc[i][3]);
        float4 v0 = {p0.x, p0.y, p1.x, p1.y};
        float4 v1 = {p2.x, p2.y, p3.x, p3.y};
        *reinterpret_cast<float4*>(&ap[(size_t)row * HN + half * 64 + tc * 8])     = v0;
        *reinterpret_cast<float4*>(&ap[(size_t)row * HN + half * 64 + tc * 8 + 4]) = v1;
    }
}

// ===========================================================================
// Kernel 3: sequential prefix scan: S_0 = 0; S_{c+1} = g^L * S_c + A_c.
// ===========================================================================
__global__ void scan_kernel()
{
    int idx = blockIdx.x * blockDim.x + threadIdx.x;
    if (idx >= BN * HN * HN) return;
    int b = idx / (HN * HN);
    int e = idx % (HN * HN);
    const float gL = powf(GAMMA, (float)LN);
    float S = 0.0f;
    for (int c = 0; c < NCN; ++c) {
        size_t off = (size_t)(b * NCN + c) * HN * HN + e;
        g_S[off] = S;
        S = fmaf(S, gL, g_A[off]);
    }
}

// ===========================================================================
// Kernel 4: per-chunk output, split into two 64-row halves (z dim).
//   P[i][j] = (q_s[i] . k[j]) * g^(i-j) (causal)
//   out     = P @ V  +  (g^i * q_s) @ S_c
// 128 threads, 64x128 output per block, 8x8 micro via FFMA2.
// Half 0 skips the upper-triangle jt tiles in P@V.
// ===========================================================================
__global__ __launch_bounds__(128) void out_kernel(float* __restrict__ out)
{
    __shared__ float Ast[16][68];    // q / P-stripe staging (64-wide)
    __shared__ float Bst[16][132];   // k / V / S staging (128-wide)
    __shared__ float gp[128];        // gamma^0 .. gamma^127

    const int c    = blockIdx.x;
    const int b    = blockIdx.y;
    const int half = blockIdx.z;
    const size_t rowbase = (size_t)(b * TN + c * LN);
    const float* __restrict__ qp = g_q + rowbase * HN;
    const float* __restrict__ kp = g_k + rowbase * HN;
    const float* __restrict__ vp = g_v + rowbase * HN;
    const float* __restrict__ sp = g_S + (size_t)(b * NCN + c) * HN * HN;

    const int tid = threadIdx.x;
    const int tr  = tid >> 4;   // 0..7  -> local rows tr*8..
    const int tc  = tid & 15;   // 0..15 -> cols tc*8..

    gp[tid] = powf(GAMMA, (float)tid);
    __syncthreads();

    // ---------------- phase 1: P = q_s @ k^T (64 rows x 128 j) ------------
    ull pAcc[8][4];
#pragma unroll
    for (int i = 0; i < 8; ++i)
#pragma unroll
        for (int j = 0; j < 4; ++j) pAcc[i][j] = 0ull;

    for (int ht = 0; ht < 8; ++ht) {
        // q tile: local rows 0..63 of this half, cols ht*16.. -> Ast[kk][lr]
#pragma unroll
        for (int r = 0; r < 2; ++r) {
            int id  = tid + 128 * r;
            int row = id >> 2;          // 0..63 local
            int c4  = id & 3;
            float4 qv = *reinterpret_cast<const float4*>(
                &qp[(size_t)(half * 64 + row) * HN + ht * 16 + c4 * 4]);
            Ast[c4 * 4 + 0][row] = qv.x;
            Ast[c4 * 4 + 1][row] = qv.y;
            Ast[c4 * 4 + 2][row] = qv.z;
            Ast[c4 * 4 + 3][row] = qv.w;
        }
        // k tile: all 128 j rows, transposed -> Bst[kk][j]
#pragma unroll
        for (int r = 0; r < 4; ++r) {
            int id  = tid + 128 * r;
            int row = id >> 2;          // 0..127
            int c4  = id & 3;
            float4 kv = *reinterpret_cast<const float4*>(
                &kp[(size_t)row * HN + ht * 16 + c4 * 4]);
            Bst[c4 * 4 + 0][row] = kv.x;
            Bst[c4 * 4 + 1][row] = kv.y;
            Bst[c4 * 4 + 2][row] = kv.z;
            Bst[c4 * 4 + 3][row] = kv.w;
        }
        __syncthreads();
#pragma unroll
        for (int kk = 0; kk < 16; ++kk) {
            float4 a0 = *reinterpret_cast<const float4*>(&Ast[kk][tr * 8]);
            float4 a1 = *reinterpret_cast<const float4*>(&Ast[kk][tr * 8 + 4]);
            const ull* bq = reinterpret_cast<const ull*>(&Bst[kk][tc * 8]);
            ull b0 = bq[0], b1 = bq[1], b2 = bq[2], b3 = bq[3];
            ull ad[8];
            ad[0] = pack2(a0.x, a0.x); ad[1] = pack2(a0.y, a0.y);
            ad[2] = pack2(a0.z, a0.z); ad[3] = pack2(a0.w, a0.w);
            ad[4] = pack2(a1.x, a1.x); ad[5] = pack2(a1.y, a1.y);
            ad[6] = pack2(a1.z, a1.z); ad[7] = pack2(a1.w, a1.w);
#pragma unroll
            for (int i = 0; i < 8; ++i) {
                fma2(pAcc[i][0], ad[i], b0);
                fma2(pAcc[i][1], ad[i], b1);
                fma2(pAcc[i][2], ad[i], b2);
                fma2(pAcc[i][3], ad[i], b3);
            }
        }
        __syncthreads();
    }

    // decay mask (packed): P[i][j] *= g^(i-j) if i>=j else 0
#pragma unroll
    for (int ii = 0; ii < 8; ++ii) {
        int i = half * 64 + tr * 8 + ii;
#pragma unroll
        for (int jp = 0; jp < 4; ++jp) {
            int jlo = tc * 8 + 2 * jp;
            int d0 = i - jlo;
            int d1 = d0 - 1;
            float m0 = (d0 >= 0) ? gp[d0] : 0.0f;
            float m1 = (d1 >= 0) ? gp[d1] : 0.0f;
            ull pm = pack2(m0, m1);
            mul2(pAcc[ii][jp], pAcc[ii][jp], pm);
        }
    }

    // ---------------- phase 2a: out = P @ V -------------------------------
    ull oAcc[8][4];
#pragma unroll
    for (int i = 0; i < 8; ++i)
#pragma unroll
        for (int j = 0; j < 4; ++j) oAcc[i][j] = 0ull;

    const int jtmax = (half == 0) ? 4 : 8;   // half 0 rows never see j >= 64
    for (int jt = 0; jt < jtmax; ++jt) {
        // owners of P columns [jt*16, jt*16+16) write transposed stripe
        if ((tc >> 1) == jt) {
            int jbase = (tc & 1) * 8;
#pragma unroll
            for (int jp = 0; jp < 4; ++jp) {
#pragma unroll
                for (int ii = 0; ii < 8; ++ii) {
                    float2 p = unpack2(pAcc[ii][jp]);
                    Ast[jbase + 2 * jp][tr * 8 + ii]     = p.x;
                    Ast[jbase + 2 * jp + 1][tr * 8 + ii] = p.y;
                }
            }
        }
        // V tile [16 j][128 hv] natural
#pragma unroll
        for (int r = 0; r < 4; ++r) {
            int id  = tid + 128 * r;
            int row = id >> 5;
            int c4  = id & 31;
            *reinterpret_cast<float4*>(&Bst[row][c4 * 4]) =
                *reinterpret_cast<const float4*>(&vp[(size_t)(jt * 16 + row) * HN + c4 * 4]);
        }
        __syncthreads();
#pragma unroll
        for (int kk = 0; kk < 16; ++kk) {
            float4 a0 = *reinterpret_cast<const float4*>(&Ast[kk][tr * 8]);
            float4 a1 = *reinterpret_cast<const float4*>(&Ast[kk][tr * 8 + 4]);
            const ull* bq = reinterpret_cast<const ull*>(&Bst[kk][tc * 8]);
            ull b0 = bq[0], b1 = bq[1], b2 = bq[2], b3 = bq[3];
            ull ad[8];
            ad[0] = pack2(a0.x, a0.x); ad[1] = pack2(a0.y, a0.y);
            ad[2] = pack2(a0.z, a0.z); ad[3] = pack2(a0.w, a0.w);
            ad[4] = pack2(a1.x, a1.x); ad[5] = pack2(a1.y, a1.y);
            ad[6] = pack2(a1.z, a1.z); ad[7] = pack2(a1.w, a1.w);
#pragma unroll
            for (int i = 0; i < 8; ++i) {
                fma2(oAcc[i][0], ad[i], b0);
                fma2(oAcc[i][1], ad[i], b1);
                fma2(oAcc[i][2], ad[i], b2);
                fma2(oAcc[i][3], ad[i], b3);
            }
        }
        __syncthreads();
    }

    // ---------------- phase 2b: out += (g^i * q_s) @ S_c ------------------
    for (int ht = 0; ht < 8; ++ht) {
        // q tile transposed, scaled by g^i (i = chunk-local row)
#pragma unroll
        for (int r = 0; r < 2; ++r) {
            int id  = tid + 128 * r;
            int row = id >> 2;          // 0..63 local
            int c4  = id & 3;
            float g = gp[half * 64 + row];
            float4 qv = *reinterpret_cast<const float4*>(
                &qp[(size_t)(half * 64 + row) * HN + ht * 16 + c4 * 4]);
            Ast[c4 * 4 + 0][row] = qv.x * g;
            Ast[c4 * 4 + 1][row] = qv.y * g;
            Ast[c4 * 4 + 2][row] = qv.z * g;
            Ast[c4 * 4 + 3][row] = qv.w * g;
        }
        // S tile [16 hk][128 hv] natural
#pragma unroll
        for (int r = 0; r < 4; ++r) {
            int id  = tid + 128 * r;
            int row = id >> 5;
            int c4  = id & 31;
            *reinterpret_cast<float4*>(&Bst[row][c4 * 4]) =
                *reinterpret_cast<const float4*>(&sp[(size_t)(ht * 16 + row) * HN + c4 * 4]);
        }
        __syncthreads();
#pragma unroll
        for (int kk = 0; kk < 16; ++kk) {
            float4 a0 = *reinterpret_cast<const float4*>(&Ast[kk][tr * 8]);
            float4 a1 = *reinterpret_cast<const float4*>(&Ast[kk][tr * 8 + 4]);
            const ull* bq = reinterpret_cast<const ull*>(&Bst[kk][tc * 8]);
            ull b0 = bq[0], b1 = bq[1], b2 = bq[2], b3 = bq[3];
            ull ad[8];
            ad[0] = pack2(a0.x, a0.x); ad[1] = pack2(a0.y, a0.y);
            ad[2] = pack2(a0.z, a0.z); ad[3] = pack2(a0.w, a0.w);
            ad[4] = pack2(a1.x, a1.x); ad[5] = pack2(a1.y, a1.y);
            ad[6] = pack2(a1.z, a1.z); ad[7] = pack2(a1.w, a1.w);
#pragma unroll
            for (int i = 0; i < 8; ++i) {
                fma2(oAcc[i][0], ad[i], b0);
                fma2(oAcc[i][1], ad[i], b1);
                fma2(oAcc[i][2], ad[i], b2);
                fma2(oAcc[i][3], ad[i], b3);
            }
        }
        __syncthreads();
    }

    // store out rows (64 rows of this half)
#pragma unroll
    for (int i = 0; i < 8; ++i) {
        size_t row = rowbase + half * 64 + tr * 8 + i;
        float2 p0 = unpack2(oAcc[i][0]), p1 = unpack2(oAcc[i][1]);
        float2 p2 = unpack2(oAcc[i][2]), p3 = unpack2(oAcc[i][3]);
        float4 v0 = {p0.x, p0.y, p1.x, p1.y};
        float4 v1 = {p2.x, p2.y, p3.x, p3.y};
        *reinterpret_cast<float4*>(&out[row * HN + tc * 8])     = v0;
        *reinterpret_cast<float4*>(&out[row * HN + tc * 8 + 4]) = v1;
    }
}

// ===========================================================================
extern "C" void kernel_launch(void* const* d_in, const int* in_sizes, int n_in,
                              void* d_out, int out_size)
{
    const float* x  = (const float*)d_in[0];
    const float* Wq = (const float*)d_in[1];
    const float* Wk = (const float*)d_in[2];
    const float* Wv = (const float*)d_in[3];
    float* out = (float*)d_out;

    proj_kernel<<<dim3(MN / 128, 3), 256>>>(x, Wq, Wk, Wv);
    chunkkv_kernel<<<dim3(NCN, BN, 2), 128>>>();
    scan_kernel<<<(BN * HN * HN + 255) / 256, 256>>>();
    out_kernel<<<dim3(NCN, BN, 2), 128>>>(out);
}

// round 4
// speedup vs baseline: 2.2288x; 1.6968x over previous
#include <cuda_runtime.h>
#include <cuda_bf16.h>
#include <math.h>
#include <stdint.h>

// Problem constants: RetentionHead  B=4, T=4096, C=1024, H=128
#define BN 4
#define TN 4096
#define CN 1024
#define HN 128
#define LN 128                 // chunk length
#define NCN (TN / LN)          // 32 chunks per batch
#define MN (BN * TN)           // 16384 rows
#define NPROJ 384              // q|k|v concatenated
#define GAMMA 0.96875f
#define SCALE 0.03125f         // C^-0.5 = 1/32

typedef unsigned long long ull;

// ---------------- packed f32x2 helpers (FFMA2, non-proj kernels) -----------
__device__ __forceinline__ ull pack2(float lo, float hi) {
    ull r;
    asm("mov.b64 %0, {%1, %2};" : "=l"(r) : "f"(lo), "f"(hi));
    return r;
}
__device__ __forceinline__ float2 unpack2(ull v) {
    float2 f;
    asm("mov.b64 {%0, %1}, %2;" : "=f"(f.x), "=f"(f.y) : "l"(v));
    return f;
}
__device__ __forceinline__ void fma2(ull& d, ull a, ull b) {
    asm("fma.rn.f32x2 %0, %1, %2, %3;" : "=l"(d) : "l"(a), "l"(b), "l"(d));
}
__device__ __forceinline__ void mul2(ull& d, ull a, ull b) {
    asm("mul.rn.f32x2 %0, %1, %2;" : "=l"(d) : "l"(a), "l"(b));
}

// ---------------- mma.sync / ldmatrix / cp.async helpers (sm_80+ PTX) ------
__device__ __forceinline__ uint32_t smem_u32(const void* p) {
    uint32_t a;
    asm("{ .reg .u64 t; cvta.to.shared.u64 t, %1; cvt.u32.u64 %0, t; }" : "=r"(a) : "l"(p));
    return a;
}
__device__ __forceinline__ void cp16(uint32_t s, const void* g) {
    asm volatile("cp.async.cg.shared.global [%0], [%1], 16;" :: "r"(s), "l"(g));
}
__device__ __forceinline__ void cp_commit() {
    asm volatile("cp.async.commit_group;" ::: "memory");
}
__device__ __forceinline__ void ldm_x4(uint32_t* r, uint32_t addr) {
    asm volatile("ldmatrix.sync.aligned.m8n8.x4.shared.b16 {%0,%1,%2,%3}, [%4];"
                 : "=r"(r[0]), "=r"(r[1]), "=r"(r[2]), "=r"(r[3]) : "r"(addr));
}
__device__ __forceinline__ void mma_bf16(float* d, const uint32_t* a,
                                         uint32_t b0, uint32_t b1) {
    asm volatile(
        "mma.sync.aligned.m16n8k16.row.col.f32.bf16.bf16.f32 "
        "{%0,%1,%2,%3}, {%4,%5,%6,%7}, {%8,%9}, {%0,%1,%2,%3};"
        : "+f"(d[0]), "+f"(d[1]), "+f"(d[2]), "+f"(d[3])
        : "r"(a[0]), "r"(a[1]), "r"(a[2]), "r"(a[3]), "r"(b0), "r"(b1));
}
__device__ __forceinline__ uint32_t pack_bf2(float a, float b) {
    __nv_bfloat162 t = __floats2bfloat162_rn(a, b);
    return *reinterpret_cast<uint32_t*>(&t);
}

// ---------------- scratch (device globals; no allocation allowed) ----------
__device__ float g_q[MN * HN];
__device__ float g_k[MN * HN];
__device__ float g_v[MN * HN];
__device__ float g_A[BN * NCN * HN * HN];
__device__ float g_S[BN * NCN * HN * HN];
__device__ __nv_bfloat16 g_x_hi[MN * CN];        // 32 MB
__device__ __nv_bfloat16 g_x_lo[MN * CN];        // 32 MB
__device__ __nv_bfloat16 g_wt_hi[NPROJ * CN];    // W^T hi  [n][k]
__device__ __nv_bfloat16 g_wt_lo[NPROJ * CN];    // W^T lo

// ===========================================================================
// Kernel 0a: x split  fp32 -> bf16 hi/lo  (8 elems/thread)
// ===========================================================================
__global__ void xprep_kernel(const float* __restrict__ x)
{
    size_t i = (size_t)(blockIdx.x * blockDim.x + threadIdx.x) * 8;
    float4 f0 = *reinterpret_cast<const float4*>(x + i);
    float4 f1 = *reinterpret_cast<const float4*>(x + i + 4);
    float f[8] = {f0.x, f0.y, f0.z, f0.w, f1.x, f1.y, f1.z, f1.w};
    float h[8];
#pragma unroll
    for (int j = 0; j < 8; ++j)
        h[j] = __bfloat162float(__float2bfloat16_rn(f[j]));
    uint4 vh, vl;
    vh.x = pack_bf2(f[0], f[1]); vh.y = pack_bf2(f[2], f[3]);
    vh.z = pack_bf2(f[4], f[5]); vh.w = pack_bf2(f[6], f[7]);
    vl.x = pack_bf2(f[0]-h[0], f[1]-h[1]); vl.y = pack_bf2(f[2]-h[2], f[3]-h[3]);
    vl.z = pack_bf2(f[4]-h[4], f[5]-h[5]); vl.w = pack_bf2(f[6]-h[6], f[7]-h[7]);
    *reinterpret_cast<uint4*>(&g_x_hi[i]) = vh;
    *reinterpret_cast<uint4*>(&g_x_lo[i]) = vl;
}

// ===========================================================================
// Kernel 0b: W prep — transpose + split fp32 W[k][n] -> bf16 hi/lo [mat*128+n][k]
// ===========================================================================
__global__ void wprep_kernel(const float* __restrict__ Wq,
                             const float* __restrict__ Wk,
                             const float* __restrict__ Wv)
{
    int k = blockIdx.x;
    int mat = blockIdx.y;
    int n = threadIdx.x;
    const float* W = (mat == 0) ? Wq : (mat == 1) ? Wk : Wv;
    float w = W[(size_t)k * HN + n];
    __nv_bfloat16 hi = __float2bfloat16_rn(w);
    float rem = w - __bfloat162float(hi);
    size_t off = ((size_t)mat * HN + n) * CN + k;
    g_wt_hi[off] = hi;
    g_wt_lo[off] = __float2bfloat16_rn(rem);
}

// ===========================================================================
// Kernel 1: projection GEMM via mma.sync bf16 split-2 (3 products).
// D[M=16384, N=384] = X[M,K=1024] @ Wt^T.  Block tile 128x128, warp 64x32.
// cp.async double-buffered BK=32.  Output: q|k|v per blockIdx.y; q scaled.
// ===========================================================================
#define OFF_A_HI 0
#define OFF_A_LO 8192
#define OFF_B_HI 16384
#define OFF_B_LO 24576
#define BUF_SZ 32768
#define NKSTEP (CN / 32)

__device__ __forceinline__ void proj_load(int k0, uint32_t sbuf, int tid,
                                          int m0, int n0)
{
#pragma unroll
    for (int r = 0; r < 2; ++r) {
        int id  = tid + 256 * r;        // 0..511
        int row = id >> 2;              // 0..127
        int ch  = id & 3;               // 16B chunk within 64B row
        uint32_t so = (uint32_t)(row * 64 + ((ch ^ ((row >> 1) & 3)) * 16));
        const __nv_bfloat16* axh = &g_x_hi[(size_t)(m0 + row) * CN + k0 + ch * 8];
        const __nv_bfloat16* axl = &g_x_lo[(size_t)(m0 + row) * CN + k0 + ch * 8];
        const __nv_bfloat16* bwh = &g_wt_hi[(size_t)(n0 + row) * CN + k0 + ch * 8];
        const __nv_bfloat16* bwl = &g_wt_lo[(size_t)(n0 + row) * CN + k0 + ch * 8];
        cp16(sbuf + OFF_A_HI + so, axh);
        cp16(sbuf + OFF_A_LO + so, axl);
        cp16(sbuf + OFF_B_HI + so, bwh);
        cp16(sbuf + OFF_B_LO + so, bwl);
    }
    cp_commit();
}

__global__ __launch_bounds__(256) void proj_mma_kernel()
{
    extern __shared__ char sm[];
    const uint32_t sbase = smem_u32(sm);
    const int tid  = threadIdx.x;
    const int wid  = tid >> 5;
    const int lane = tid & 31;
    const int wm   = wid & 1;        // 2 warp-rows (64 M each)
    const int wn   = wid >> 1;       // 4 warp-cols (32 N each)
    const int m0   = blockIdx.x * 128;
    const int n0   = blockIdx.y * 128;

    float acc[4][4][4];
#pragma unroll
    for (int a = 0; a < 4; ++a)
#pragma unroll
        for (int b = 0; b < 4; ++b)
#pragma unroll
            for (int c = 0; c < 4; ++c) acc[a][b][c] = 0.0f;

    proj_load(0, sbase, tid, m0, n0);

    for (int ks = 0; ks < NKSTEP; ++ks) {
        const uint32_t sbuf = sbase + (uint32_t)(ks & 1) * BUF_SZ;
        if (ks + 1 < NKSTEP) {
            proj_load((ks + 1) * 32, sbase + (uint32_t)((ks + 1) & 1) * BUF_SZ,
                      tid, m0, n0);
            asm volatile("cp.async.wait_group 1;" ::: "memory");
        } else {
            asm volatile("cp.async.wait_group 0;" ::: "memory");
        }
        __syncthreads();

#pragma unroll
        for (int kk = 0; kk < 2; ++kk) {       // two k16 halves of BK=32
            uint32_t ah[4][4], al[4][4];
            const int arow = lane & 15;
            const int ach  = kk * 2 + (lane >> 4);
#pragma unroll
            for (int mf = 0; mf < 4; ++mf) {
                int row = wm * 64 + mf * 16 + arow;
                uint32_t so = (uint32_t)(row * 64 + ((ach ^ ((row >> 1) & 3)) * 16));
                ldm_x4(ah[mf], sbuf + OFF_A_HI + so);
                ldm_x4(al[mf], sbuf + OFF_A_LO + so);
            }
            uint32_t bh[2][4], bl[2][4];
            const int brow = (lane & 7) + ((lane >> 4) & 1) * 8;
            const int bch  = kk * 2 + ((lane >> 3) & 1);
#pragma unroll
            for (int nf2 = 0; nf2 < 2; ++nf2) {
                int row = wn * 32 + nf2 * 16 + brow;
                uint32_t so = (uint32_t)(row * 64 + ((bch ^ ((row >> 1) & 3)) * 16));
                ldm_x4(bh[nf2], sbuf + OFF_B_HI + so);
                ldm_x4(bl[nf2], sbuf + OFF_B_LO + so);
            }
#pragma unroll
            for (int mf = 0; mf < 4; ++mf) {
#pragma unroll
                for (int nf = 0; nf < 4; ++nf) {
                    uint32_t h0 = bh[nf >> 1][(nf & 1) * 2];
                    uint32_t h1 = bh[nf >> 1][(nf & 1) * 2 + 1];
                    uint32_t l0 = bl[nf >> 1][(nf & 1) * 2];
                    uint32_t l1 = bl[nf >> 1][(nf & 1) * 2 + 1];
                    mma_bf16(acc[mf][nf], ah[mf], h0, h1);   // hi*hi
                    mma_bf16(acc[mf][nf], al[mf], h0, h1);   // lo*hi
                    mma_bf16(acc[mf][nf], ah[mf], l0, l1);   // hi*lo
                }
            }
        }
        __syncthreads();
    }

    // epilogue: blockIdx.y selects q/k/v
    float* outp = (blockIdx.y == 0) ? g_q : (blockIdx.y == 1) ? g_k : g_v;
    const float sc = (blockIdx.y == 0) ? SCALE : 1.0f;
    const int r0 = lane >> 2;
    const int cp = (lane & 3) * 2;
#pragma unroll
    for (int mf = 0; mf < 4; ++mf) {
#pragma unroll
        for (int nf = 0; nf < 4; ++nf) {
            int row = m0 + wm * 64 + mf * 16 + r0;
            int col = wn * 32 + nf * 8 + cp;
            float2 v0 = {acc[mf][nf][0] * sc, acc[mf][nf][1] * sc};
            float2 v1 = {acc[mf][nf][2] * sc, acc[mf][nf][3] * sc};
            *reinterpret_cast<float2*>(&outp[(size_t)row * HN + col])       = v0;
            *reinterpret_cast<float2*>(&outp[(size_t)(row + 8) * HN + col]) = v1;
        }
    }
}

// ===========================================================================
// Kernel 2: A_c[hk][hv] = sum_j g^(L-j) k[j,hk] v[j,hv]   (unchanged, FFMA2)
// ===========================================================================
__global__ __launch_bounds__(128) void chunkkv_kernel()
{
    __shared__ float Ks[16][132];
    __shared__ float Vs[16][68];
    __shared__ float gp[132];

    const int c    = blockIdx.x;
    const int b    = blockIdx.y;
    const int half = blockIdx.z;
    const float* __restrict__ kp = g_k + (size_t)(b * TN + c * LN) * HN;
    const float* __restrict__ vp = g_v + (size_t)(b * TN + c * LN) * HN;
    float* __restrict__ ap = g_A + (size_t)(b * NCN + c) * HN * HN;

    const int tid = threadIdx.x;
    const int tr  = tid >> 3;
    const int tc  = tid & 7;

    gp[tid] = powf(GAMMA, (float)tid);
    if (tid == 0) gp[128] = powf(GAMMA, 128.0f);
    __syncthreads();

    ull acc[8][4];
#pragma unroll
    for (int i = 0; i < 8; ++i)
#pragma unroll
        for (int j = 0; j < 4; ++j) acc[i][j] = 0ull;

    for (int jt = 0; jt < 8; ++jt) {
#pragma unroll
        for (int r = 0; r < 4; ++r) {
            int id  = tid + 128 * r;
            int row = id >> 5;
            int c4  = id & 31;
            int j   = jt * 16 + row;
            float w = gp[LN - j];
            float4 kv = *reinterpret_cast<const float4*>(&kp[(size_t)j * HN + c4 * 4]);
            kv.x *= w; kv.y *= w; kv.z *= w; kv.w *= w;
            *reinterpret_cast<float4*>(&Ks[row][c4 * 4]) = kv;
        }
#pragma unroll
        for (int r = 0; r < 2; ++r) {
            int id  = tid + 128 * r;
            int row = id >> 4;
            int c4  = id & 15;
            int j   = jt * 16 + row;
            *reinterpret_cast<float4*>(&Vs[row][c4 * 4]) =
                *reinterpret_cast<const float4*>(&vp[(size_t)j * HN + half * 64 + c4 * 4]);
        }
        __syncthreads();
#pragma unroll
        for (int kk = 0; kk < 16; ++kk) {
            float4 a0 = *reinterpret_cast<const float4*>(&Ks[kk][tr * 8]);
            float4 a1 = *reinterpret_cast<const float4*>(&Ks[kk][tr * 8 + 4]);
            const ull* bq = reinterpret_cast<const ull*>(&Vs[kk][tc * 8]);
            ull b0 = bq[0], b1 = bq[1], b2 = bq[2], b3 = bq[3];
            ull ad[8];
            ad[0] = pack2(a0.x, a0.x); ad[1] = pack2(a0.y, a0.y);
            ad[2] = pack2(a0.z, a0.z); ad[3] = pack2(a0.w, a0.w);
            ad[4] = pack2(a1.x, a1.x); ad[5] = pack2(a1.y, a1.y);
            ad[6] = pack2(a1.z, a1.z); ad[7] = pack2(a1.w, a1.w);
#pragma unroll
            for (int i = 0; i < 8; ++i) {
                fma2(acc[i][0], ad[i], b0);
                fma2(acc[i][1], ad[i], b1);
                fma2(acc[i][2], ad[i], b2);
                fma2(acc[i][3], ad[i], b3);
            }
        }
        __syncthreads();
    }
#pragma unroll
    for (int i = 0; i < 8; ++i) {
        int row = tr * 8 + i;
        float2 p0 = unpack2(acc[i][0]), p1 = unpack2(acc[i][1]);
        float2 p2 = unpack2(acc[i][2]), p3 = unpack2(acc[i][3]);
        float4 v0 = {p0.x, p0.y, p1.x, p1.y};
        float4 v1 = {p2.x, p2.y, p3.x, p3.y};
        *reinterpret_cast<float4*>(&ap[(size_t)row * HN + half * 64 + tc * 8])     = v0;
        *reinterpret_cast<float4*>(&ap[(size_t)row * HN + half * 64 + tc * 8 + 4]) = v1;
    }
}

// ===========================================================================
// Kernel 3: prefix scan: S_0 = 0; S_{c+1} = g^L * S_c + A_c.  (unchanged)
// ===========================================================================
__global__ void scan_kernel()
{
    int idx = blockIdx.x * blockDim.x + threadIdx.x;
    if (idx >= BN * HN * HN) return;
    int b = idx / (HN * HN);
    int e = idx % (HN * HN);
    const float gL = powf(GAMMA, (float)LN);
    float S = 0.0f;
    for (int c = 0; c < NCN; ++c) {
        size_t off = (size_t)(b * NCN + c) * HN * HN + e;
        g_S[off] = S;
        S = fmaf(S, gL, g_A[off]);
    }
}

// ===========================================================================
// Kernel 4: per-chunk output (unchanged, FFMA2)
// ===========================================================================
__global__ __launch_bounds__(128) void out_kernel(float* __restrict__ out)
{
    __shared__ float Ast[16][68];
    __shared__ float Bst[16][132];
    __shared__ float gp[128];

    const int c    = blockIdx.x;
    const int b    = blockIdx.y;
    const int half = blockIdx.z;
    const size_t rowbase = (size_t)(b * TN + c * LN);
    const float* __restrict__ qp = g_q + rowbase * HN;
    const float* __restrict__ kp = g_k + rowbase * HN;
    const float* __restrict__ vp = g_v + rowbase * HN;
    const float* __restrict__ sp = g_S + (size_t)(b * NCN + c) * HN * HN;

    const int tid = threadIdx.x;
    const int tr  = tid >> 4;
    const int tc  = tid & 15;

    gp[tid] = powf(GAMMA, (float)tid);
    __syncthreads();

    ull pAcc[8][4];
#pragma unroll
    for (int i = 0; i < 8; ++i)
#pragma unroll
        for (int j = 0; j < 4; ++j) pAcc[i][j] = 0ull;

    for (int ht = 0; ht < 8; ++ht) {
#pragma unroll
        for (int r = 0; r < 2; ++r) {
            int id  = tid + 128 * r;
            int row = id >> 2;
            int c4  = id & 3;
            float4 qv = *reinterpret_cast<const float4*>(
                &qp[(size_t)(half * 64 + row) * HN + ht * 16 + c4 * 4]);
            Ast[c4 * 4 + 0][row] = qv.x;
            Ast[c4 * 4 + 1][row] = qv.y;
            Ast[c4 * 4 + 2][row] = qv.z;
            Ast[c4 * 4 + 3][row] = qv.w;
        }
#pragma unroll
        for (int r = 0; r < 4; ++r) {
            int id  = tid + 128 * r;
            int row = id >> 2;
            int c4  = id & 3;
            float4 kv = *reinterpret_cast<const float4*>(
                &kp[(size_t)row * HN + ht * 16 + c4 * 4]);
            Bst[c4 * 4 + 0][row] = kv.x;
            Bst[c4 * 4 + 1][row] = kv.y;
            Bst[c4 * 4 + 2][row] = kv.z;
            Bst[c4 * 4 + 3][row] = kv.w;
        }
        __syncthreads();
#pragma unroll
        for (int kk = 0; kk < 16; ++kk) {
            float4 a0 = *reinterpret_cast<const float4*>(&Ast[kk][tr * 8]);
            float4 a1 = *reinterpret_cast<const float4*>(&Ast[kk][tr * 8 + 4]);
            const ull* bq = reinterpret_cast<const ull*>(&Bst[kk][tc * 8]);
            ull b0 = bq[0], b1 = bq[1], b2 = bq[2], b3 = bq[3];
            ull ad[8];
            ad[0] = pack2(a0.x, a0.x); ad[1] = pack2(a0.y, a0.y);
            ad[2] = pack2(a0.z, a0.z); ad[3] = pack2(a0.w, a0.w);
            ad[4] = pack2(a1.x, a1.x); ad[5] = pack2(a1.y, a1.y);
            ad[6] = pack2(a1.z, a1.z); ad[7] = pack2(a1.w, a1.w);
#pragma unroll
            for (int i = 0; i < 8; ++i) {
                fma2(pAcc[i][0], ad[i], b0);
                fma2(pAcc[i][1], ad[i], b1);
                fma2(pAcc[i][2], ad[i], b2);
                fma2(pAcc[i][3], ad[i], b3);
            }
        }
        __syncthreads();
    }

#pragma unroll
    for (int ii = 0; ii < 8; ++ii) {
        int i = half * 64 + tr * 8 + ii;
#pragma unroll
        for (int jp = 0; jp < 4; ++jp) {
            int jlo = tc * 8 + 2 * jp;
            int d0 = i - jlo;
            int d1 = d0 - 1;
            float m0 = (d0 >= 0) ? gp[d0] : 0.0f;
            float m1 = (d1 >= 0) ? gp[d1] : 0.0f;
            ull pm = pack2(m0, m1);
            mul2(pAcc[ii][jp], pAcc[ii][jp], pm);
        }
    }

    ull oAcc[8][4];
#pragma unroll
    for (int i = 0; i < 8; ++i)
#pragma unroll
        for (int j = 0; j < 4; ++j) oAcc[i][j] = 0ull;

    const int jtmax = (half == 0) ? 4 : 8;
    for (int jt = 0; jt < jtmax; ++jt) {
        if ((tc >> 1) == jt) {
            int jbase = (tc & 1) * 8;
#pragma unroll
            for (int jp = 0; jp < 4; ++jp) {
#pragma unroll
                for (int ii = 0; ii < 8; ++ii) {
                    float2 p = unpack2(pAcc[ii][jp]);
                    Ast[jbase + 2 * jp][tr * 8 + ii]     = p.x;
                    Ast[jbase + 2 * jp + 1][tr * 8 + ii] = p.y;
                }
            }
        }
#pragma unroll
        for (int r = 0; r < 4; ++r) {
            int id  = tid + 128 * r;
            int row = id >> 5;
            int c4  = id & 31;
            *reinterpret_cast<float4*>(&Bst[row][c4 * 4]) =
                *reinterpret_cast<const float4*>(&vp[(size_t)(jt * 16 + row) * HN + c4 * 4]);
        }
        __syncthreads();
#pragma unroll
        for (int kk = 0; kk < 16; ++kk) {
            float4 a0 = *reinterpret_cast<const float4*>(&Ast[kk][tr * 8]);
            float4 a1 = *reinterpret_cast<const float4*>(&Ast[kk][tr * 8 + 4]);
            const ull* bq = reinterpret_cast<const ull*>(&Bst[kk][tc * 8]);
            ull b0 = bq[0], b1 = bq[1], b2 = bq[2], b3 = bq[3];
            ull ad[8];
            ad[0] = pack2(a0.x, a0.x); ad[1] = pack2(a0.y, a0.y);
            ad[2] = pack2(a0.z, a0.z); ad[3] = pack2(a0.w, a0.w);
            ad[4] = pack2(a1.x, a1.x); ad[5] = pack2(a1.y, a1.y);
            ad[6] = pack2(a1.z, a1.z); ad[7] = pack2(a1.w, a1.w);
#pragma unroll
            for (int i = 0; i < 8; ++i) {
                fma2(oAcc[i][0], ad[i], b0);
                fma2(oAcc[i][1], ad[i], b1);
                fma2(oAcc[i][2], ad[i], b2);
                fma2(oAcc[i][3], ad[i], b3);
            }
        }
        __syncthreads();
    }

    for (int ht = 0; ht < 8; ++ht) {
#pragma unroll
        for (int r = 0; r < 2; ++r) {
            int id  = tid + 128 * r;
            int row = id >> 2;
            int c4  = id & 3;
            float g = gp[half * 64 + row];
            float4 qv = *reinterpret_cast<const float4*>(
                &qp[(size_t)(half * 64 + row) * HN + ht * 16 + c4 * 4]);
            Ast[c4 * 4 + 0][row] = qv.x * g;
            Ast[c4 * 4 + 1][row] = qv.y * g;
            Ast[c4 * 4 + 2][row] = qv.z * g;
            Ast[c4 * 4 + 3][row] = qv.w * g;
        }
#pragma unroll
        for (int r = 0; r < 4; ++r) {
            int id  = tid + 128 * r;
            int row = id >> 5;
            int c4  = id & 31;
            *reinterpret_cast<float4*>(&Bst[row][c4 * 4]) =
                *reinterpret_cast<const float4*>(&sp[(size_t)(ht * 16 + row) * HN + c4 * 4]);
        }
        __syncthreads();
#pragma unroll
        for (int kk = 0; kk < 16; ++kk) {
            float4 a0 = *reinterpret_cast<const float4*>(&Ast[kk][tr * 8]);
            float4 a1 = *reinterpret_cast<const float4*>(&Ast[kk][tr * 8 + 4]);
            const ull* bq = reinterpret_cast<const ull*>(&Bst[kk][tc * 8]);
            ull b0 = bq[0], b1 = bq[1], b2 = bq[2], b3 = bq[3];
            ull ad[8];
            ad[0] = pack2(a0.x, a0.x); ad[1] = pack2(a0.y, a0.y);
            ad[2] = pack2(a0.z, a0.z); ad[3] = pack2(a0.w, a0.w);
            ad[4] = pack2(a1.x, a1.x); ad[5] = pack2(a1.y, a1.y);
            ad[6] = pack2(a1.z, a1.z); ad[7] = pack2(a1.w, a1.w);
#pragma unroll
            for (int i = 0; i < 8; ++i) {
                fma2(oAcc[i][0], ad[i], b0);
                fma2(oAcc[i][1], ad[i], b1);
                fma2(oAcc[i][2], ad[i], b2);
                fma2(oAcc[i][3], ad[i], b3);
            }
        }
        __syncthreads();
    }

#pragma unroll
    for (int i = 0; i < 8; ++i) {
        size_t row = rowbase + half * 64 + tr * 8 + i;
        float2 p0 = unpack2(oAcc[i][0]), p1 = unpack2(oAcc[i][1]);
        float2 p2 = unpack2(oAcc[i][2]), p3 = unpack2(oAcc[i][3]);
        float4 v0 = {p0.x, p0.y, p1.x, p1.y};
        float4 v1 = {p2.x, p2.y, p3.x, p3.y};
        *reinterpret_cast<float4*>(&out[row * HN + tc * 8])     = v0;
        *reinterpret_cast<float4*>(&out[row * HN + tc * 8 + 4]) = v1;
    }
}

// ===========================================================================
extern "C" void kernel_launch(void* const* d_in, const int* in_sizes, int n_in,
                              void* d_out, int out_size)
{
    const float* x  = (const float*)d_in[0];
    const float* Wq = (const float*)d_in[1];
    const float* Wk = (const float*)d_in[2];
    const float* Wv = (const float*)d_in[3];
    float* out = (float*)d_out;

    cudaFuncSetAttribute(proj_mma_kernel, cudaFuncAttributeMaxDynamicSharedMemorySize,
                         2 * BUF_SZ);

    xprep_kernel<<<(MN * CN / 8) / 256, 256>>>(x);
    wprep_kernel<<<dim3(CN, 3), HN>>>(Wq, Wk, Wv);
    proj_mma_kernel<<<dim3(MN / 128, 3), 256, 2 * BUF_SZ>>>();
    chunkkv_kernel<<<dim3(NCN, BN, 2), 128>>>();
    scan_kernel<<<(BN * HN * HN + 255) / 256, 256>>>();
    out_kernel<<<dim3(NCN, BN, 2), 128>>>(out);
}

// round 5
// speedup vs baseline: 2.4134x; 1.0828x over previous
#include <cuda_runtime.h>
#include <cuda_bf16.h>
#include <math.h>
#include <stdint.h>

// Problem constants: RetentionHead  B=4, T=4096, C=1024, H=128
#define BN 4
#define TN 4096
#define CN 1024
#define HN 128
#define LN 128
#define NCN (TN / LN)          // 32 chunks per batch
#define MN (BN * TN)           // 16384 rows
#define NPROJ 384
#define GAMMA 0.96875f
#define SCALE 0.03125f         // C^-0.5

typedef unsigned long long ull;

// ---------------- mma.sync / ldmatrix / cp.async helpers -------------------
__device__ __forceinline__ uint32_t smem_u32(const void* p) {
    uint32_t a;
    asm("{ .reg .u64 t; cvta.to.shared.u64 t, %1; cvt.u32.u64 %0, t; }" : "=r"(a) : "l"(p));
    return a;
}
__device__ __forceinline__ void cp16(uint32_t s, const void* g) {
    asm volatile("cp.async.cg.shared.global [%0], [%1], 16;" :: "r"(s), "l"(g));
}
__device__ __forceinline__ void cp_commit() {
    asm volatile("cp.async.commit_group;" ::: "memory");
}
__device__ __forceinline__ void ldm_x4(uint32_t* r, uint32_t addr) {
    asm volatile("ldmatrix.sync.aligned.m8n8.x4.shared.b16 {%0,%1,%2,%3}, [%4];"
                 : "=r"(r[0]), "=r"(r[1]), "=r"(r[2]), "=r"(r[3]) : "r"(addr));
}
__device__ __forceinline__ void ldm_x4_t(uint32_t* r, uint32_t addr) {
    asm volatile("ldmatrix.sync.aligned.m8n8.x4.trans.shared.b16 {%0,%1,%2,%3}, [%4];"
                 : "=r"(r[0]), "=r"(r[1]), "=r"(r[2]), "=r"(r[3]) : "r"(addr));
}
__device__ __forceinline__ void mma_bf16(float* d, const uint32_t* a,
                                         uint32_t b0, uint32_t b1) {
    asm volatile(
        "mma.sync.aligned.m16n8k16.row.col.f32.bf16.bf16.f32 "
        "{%0,%1,%2,%3}, {%4,%5,%6,%7}, {%8,%9}, {%0,%1,%2,%3};"
        : "+f"(d[0]), "+f"(d[1]), "+f"(d[2]), "+f"(d[3])
        : "r"(a[0]), "r"(a[1]), "r"(a[2]), "r"(a[3]), "r"(b0), "r"(b1));
}
// 3-product split-2 mma: hi*hi + lo*hi + hi*lo
__device__ __forceinline__ void mma3(float* d, const uint32_t* ah, const uint32_t* al,
                                     uint32_t bh0, uint32_t bh1,
                                     uint32_t bl0, uint32_t bl1) {
    mma_bf16(d, ah, bh0, bh1);
    mma_bf16(d, al, bh0, bh1);
    mma_bf16(d, ah, bl0, bl1);
}
__device__ __forceinline__ uint32_t pack_bf2(float a, float b) {
    __nv_bfloat162 t = __floats2bfloat162_rn(a, b);
    return *reinterpret_cast<uint32_t*>(&t);
}
// split pair of floats into bf16 hi and lo packed words
__device__ __forceinline__ void split_pair(float a, float b, uint32_t& hi, uint32_t& lo) {
    __nv_bfloat16 ah = __float2bfloat16_rn(a);
    __nv_bfloat16 bh = __float2bfloat16_rn(b);
    __nv_bfloat162 hh; hh.x = ah; hh.y = bh;
    hi = *reinterpret_cast<uint32_t*>(&hh);
    lo = pack_bf2(a - __bfloat162float(ah), b - __bfloat162float(bh));
}

// ---------------- scratch (device globals) ---------------------------------
__device__ float g_k[MN * HN];                   // fp32 k (for decayed split)
__device__ float g_A[BN * NCN * HN * HN];
__device__ __nv_bfloat16 g_qh[MN * HN], g_ql[MN * HN];
__device__ __nv_bfloat16 g_kh[MN * HN], g_kl[MN * HN];
__device__ __nv_bfloat16 g_vh[MN * HN], g_vl[MN * HN];
__device__ __nv_bfloat16 g_Sh[BN * NCN * HN * HN], g_Sl[BN * NCN * HN * HN];
__device__ __nv_bfloat16 g_x_hi[MN * CN];
__device__ __nv_bfloat16 g_x_lo[MN * CN];
__device__ __nv_bfloat16 g_wt_hi[NPROJ * CN];
__device__ __nv_bfloat16 g_wt_lo[NPROJ * CN];

// ===========================================================================
// Kernel 0a: x split  fp32 -> bf16 hi/lo
// ===========================================================================
__global__ void xprep_kernel(const float* __restrict__ x)
{
    size_t i = (size_t)(blockIdx.x * blockDim.x + threadIdx.x) * 8;
    float4 f0 = *reinterpret_cast<const float4*>(x + i);
    float4 f1 = *reinterpret_cast<const float4*>(x + i + 4);
    float f[8] = {f0.x, f0.y, f0.z, f0.w, f1.x, f1.y, f1.z, f1.w};
    uint4 vh, vl;
    uint32_t* ph = &vh.x;
    uint32_t* pl = &vl.x;
#pragma unroll
    for (int j = 0; j < 4; ++j) split_pair(f[2*j], f[2*j+1], ph[j], pl[j]);
    *reinterpret_cast<uint4*>(&g_x_hi[i]) = vh;
    *reinterpret_cast<uint4*>(&g_x_lo[i]) = vl;
}

// ===========================================================================
// Kernel 0b: W prep — transpose + split
// ===========================================================================
__global__ void wprep_kernel(const float* __restrict__ Wq,
                             const float* __restrict__ Wk,
                             const float* __restrict__ Wv)
{
    int k = blockIdx.x;
    int mat = blockIdx.y;
    int n = threadIdx.x;
    const float* W = (mat == 0) ? Wq : (mat == 1) ? Wk : Wv;
    float w = W[(size_t)k * HN + n];
    __nv_bfloat16 hi = __float2bfloat16_rn(w);
    size_t off = ((size_t)mat * HN + n) * CN + k;
    g_wt_hi[off] = hi;
    g_wt_lo[off] = __float2bfloat16_rn(w - __bfloat162float(hi));
}

// ===========================================================================
// Kernel 1: projection GEMM via mma.sync bf16 split-2.
// Epilogue emits bf16 hi/lo of q (scaled), k, v; fp32 k kept for chunkkv.
// ===========================================================================
#define OFF_A_HI 0
#define OFF_A_LO 8192
#define OFF_B_HI 16384
#define OFF_B_LO 24576
#define BUF_SZ 32768
#define NKSTEP (CN / 32)

__device__ __forceinline__ void proj_load(int k0, uint32_t sbuf, int tid,
                                          int m0, int n0)
{
#pragma unroll
    for (int r = 0; r < 2; ++r) {
        int id  = tid + 256 * r;
        int row = id >> 2;
        int ch  = id & 3;
        uint32_t so = (uint32_t)(row * 64 + ((ch ^ ((row >> 1) & 3)) * 16));
        cp16(sbuf + OFF_A_HI + so, &g_x_hi[(size_t)(m0 + row) * CN + k0 + ch * 8]);
        cp16(sbuf + OFF_A_LO + so, &g_x_lo[(size_t)(m0 + row) * CN + k0 + ch * 8]);
        cp16(sbuf + OFF_B_HI + so, &g_wt_hi[(size_t)(n0 + row) * CN + k0 + ch * 8]);
        cp16(sbuf + OFF_B_LO + so, &g_wt_lo[(size_t)(n0 + row) * CN + k0 + ch * 8]);
    }
    cp_commit();
}

__global__ __launch_bounds__(256) void proj_mma_kernel()
{
    extern __shared__ char sm[];
    const uint32_t sbase = smem_u32(sm);
    const int tid  = threadIdx.x;
    const int wid  = tid >> 5;
    const int lane = tid & 31;
    const int wm   = wid & 1;
    const int wn   = wid >> 1;
    const int m0   = blockIdx.x * 128;
    const int n0   = blockIdx.y * 128;

    float acc[4][4][4];
#pragma unroll
    for (int a = 0; a < 4; ++a)
#pragma unroll
        for (int b = 0; b < 4; ++b)
#pragma unroll
            for (int c = 0; c < 4; ++c) acc[a][b][c] = 0.0f;

    proj_load(0, sbase, tid, m0, n0);

    for (int ks = 0; ks < NKSTEP; ++ks) {
        const uint32_t sbuf = sbase + (uint32_t)(ks & 1) * BUF_SZ;
        if (ks + 1 < NKSTEP) {
            proj_load((ks + 1) * 32, sbase + (uint32_t)((ks + 1) & 1) * BUF_SZ,
                      tid, m0, n0);
            asm volatile("cp.async.wait_group 1;" ::: "memory");
        } else {
            asm volatile("cp.async.wait_group 0;" ::: "memory");
        }
        __syncthreads();

#pragma unroll
        for (int kk = 0; kk < 2; ++kk) {
            uint32_t ah[4][4], al[4][4];
            const int arow = lane & 15;
            const int ach  = kk * 2 + (lane >> 4);
#pragma unroll
            for (int mf = 0; mf < 4; ++mf) {
                int row = wm * 64 + mf * 16 + arow;
                uint32_t so = (uint32_t)(row * 64 + ((ach ^ ((row >> 1) & 3)) * 16));
                ldm_x4(ah[mf], sbuf + OFF_A_HI + so);
                ldm_x4(al[mf], sbuf + OFF_A_LO + so);
            }
            uint32_t bh[2][4], bl[2][4];
            const int brow = (lane & 7) + ((lane >> 4) & 1) * 8;
            const int bch  = kk * 2 + ((lane >> 3) & 1);
#pragma unroll
            for (int nf2 = 0; nf2 < 2; ++nf2) {
                int row = wn * 32 + nf2 * 16 + brow;
                uint32_t so = (uint32_t)(row * 64 + ((bch ^ ((row >> 1) & 3)) * 16));
                ldm_x4(bh[nf2], sbuf + OFF_B_HI + so);
                ldm_x4(bl[nf2], sbuf + OFF_B_LO + so);
            }
#pragma unroll
            for (int mf = 0; mf < 4; ++mf) {
#pragma unroll
                for (int nf = 0; nf < 4; ++nf) {
                    mma3(acc[mf][nf], ah[mf], al[mf],
                         bh[nf >> 1][(nf & 1) * 2], bh[nf >> 1][(nf & 1) * 2 + 1],
                         bl[nf >> 1][(nf & 1) * 2], bl[nf >> 1][(nf & 1) * 2 + 1]);
                }
            }
        }
        __syncthreads();
    }

    // epilogue: write bf16 splits (+ fp32 k for mat 1)
    const int which = blockIdx.y;
    const float sc = (which == 0) ? SCALE : 1.0f;
    __nv_bfloat16* dsth = (which == 0) ? g_qh : (which == 1) ? g_kh : g_vh;
    __nv_bfloat16* dstl = (which == 0) ? g_ql : (which == 1) ? g_kl : g_vl;
    const int r0 = lane >> 2;
    const int c0 = (lane & 3) * 2;
#pragma unroll
    for (int mf = 0; mf < 4; ++mf) {
#pragma unroll
        for (int nf = 0; nf < 4; ++nf) {
            int row = m0 + wm * 64 + mf * 16 + r0;
            int col = wn * 32 + nf * 8 + c0;
            float d0 = acc[mf][nf][0] * sc, d1 = acc[mf][nf][1] * sc;
            float d2 = acc[mf][nf][2] * sc, d3 = acc[mf][nf][3] * sc;
            if (which == 1) {
                float2 v0 = {d0, d1}, v1 = {d2, d3};
                *reinterpret_cast<float2*>(&g_k[(size_t)row * HN + col])       = v0;
                *reinterpret_cast<float2*>(&g_k[(size_t)(row + 8) * HN + col]) = v1;
            }
            uint32_t h0, l0, h1, l1;
            split_pair(d0, d1, h0, l0);
            split_pair(d2, d3, h1, l1);
            *reinterpret_cast<uint32_t*>(&dsth[(size_t)row * HN + col])       = h0;
            *reinterpret_cast<uint32_t*>(&dstl[(size_t)row * HN + col])       = l0;
            *reinterpret_cast<uint32_t*>(&dsth[(size_t)(row + 8) * HN + col]) = h1;
            *reinterpret_cast<uint32_t*>(&dstl[(size_t)(row + 8) * HN + col]) = l1;
        }
    }
}

// ===========================================================================
// Kernel 2: chunkkv via mma.  A_c[hk][hv] = sum_j g^(L-j) k[j,hk] v[j,hv]
// A-operand = decayed-k (runtime split), trans-ldmatrix from [j][hk].
// B-operand = v splits, trans-ldmatrix from [j][hv].
// grid (NC, B), 256 thr, warp grid 2x4 (64x32 tiles).
// ===========================================================================
__global__ __launch_bounds__(256) void chunkkv_mma()
{
    __shared__ __align__(16) char KHI[8192], KLO[8192], VHI[8192], VLO[8192];
    __shared__ float gp[132];

    const int c = blockIdx.x;
    const int b = blockIdx.y;
    const size_t rowbase = (size_t)(b * TN + c * LN);
    const float* __restrict__ kp = g_k + rowbase * HN;
    const __nv_bfloat16* __restrict__ vhp = g_vh + rowbase * HN;
    const __nv_bfloat16* __restrict__ vlp = g_vl + rowbase * HN;
    float* __restrict__ ap = g_A + (size_t)(b * NCN + c) * HN * HN;

    const int tid  = threadIdx.x;
    const int wid  = tid >> 5;
    const int lane = tid & 31;
    const int wm   = wid & 1;
    const int wn   = wid >> 1;

    if (tid < 132) gp[tid] = powf(GAMMA, (float)tid);
    const uint32_t skh = smem_u32(KHI), skl = smem_u32(KLO);
    const uint32_t svh = smem_u32(VHI), svl = smem_u32(VLO);
    __syncthreads();

    float acc[4][4][4];
#pragma unroll
    for (int a = 0; a < 4; ++a)
#pragma unroll
        for (int e = 0; e < 4; ++e)
#pragma unroll
            for (int f = 0; f < 4; ++f) acc[a][e][f] = 0.0f;

    for (int jt = 0; jt < 4; ++jt) {
        __syncthreads();
        // decayed k split stripe [32 j][128 hk]
#pragma unroll
        for (int r = 0; r < 2; ++r) {
            int id  = tid + 256 * r;
            int row = id >> 4;
            int ch  = id & 15;
            int j   = jt * 32 + row;
            float w = gp[LN - j];
            const float* src = &kp[(size_t)j * HN + ch * 8];
            float4 f0 = *reinterpret_cast<const float4*>(src);
            float4 f1 = *reinterpret_cast<const float4*>(src + 4);
            float f[8] = {f0.x*w, f0.y*w, f0.z*w, f0.w*w, f1.x*w, f1.y*w, f1.z*w, f1.w*w};
            uint4 vh4, vl4;
            uint32_t* ph = &vh4.x;
            uint32_t* pl = &vl4.x;
#pragma unroll
            for (int q = 0; q < 4; ++q) split_pair(f[2*q], f[2*q+1], ph[q], pl[q]);
            uint32_t dst = (uint32_t)(row * 256 + ((ch ^ (row & 7)) * 16));
            *reinterpret_cast<uint4*>(KHI + dst) = vh4;
            *reinterpret_cast<uint4*>(KLO + dst) = vl4;
        }
        // v split stripe [32 j][128 hv]
#pragma unroll
        for (int r = 0; r < 2; ++r) {
            int id  = tid + 256 * r;
            int row = id >> 4;
            int ch  = id & 15;
            int j   = jt * 32 + row;
            uint4 dh = *reinterpret_cast<const uint4*>(&vhp[(size_t)j * HN + ch * 8]);
            uint4 dl = *reinterpret_cast<const uint4*>(&vlp[(size_t)j * HN + ch * 8]);
            uint32_t dst = (uint32_t)(row * 256 + ((ch ^ (row & 7)) * 16));
            *reinterpret_cast<uint4*>(VHI + dst) = dh;
            *reinterpret_cast<uint4*>(VLO + dst) = dl;
        }
        __syncthreads();

#pragma unroll
        for (int kk = 0; kk < 2; ++kk) {
            // A trans: from [j][hk], m=hk
            uint32_t ah[4][4], al[4][4];
            const int arow = kk * 16 + (lane & 7) + ((lane >> 4) & 1) * 8;
#pragma unroll
            for (int mf = 0; mf < 4; ++mf) {
                int ach = wm * 8 + mf * 2 + ((lane >> 3) & 1);
                uint32_t so = (uint32_t)(arow * 256 + ((ach ^ (arow & 7)) * 16));
                ldm_x4_t(ah[mf], skh + so);
                ldm_x4_t(al[mf], skl + so);
            }
            // B trans: from [j][hv], n=hv
            uint32_t bh[2][4], bl[2][4];
            const int brow = kk * 16 + (lane & 7) + ((lane >> 3) & 1) * 8;
#pragma unroll
            for (int nf2 = 0; nf2 < 2; ++nf2) {
                int bch = wn * 4 + nf2 * 2 + ((lane >> 4) & 1);
                uint32_t so = (uint32_t)(brow * 256 + ((bch ^ (brow & 7)) * 16));
                ldm_x4_t(bh[nf2], svh + so);
                ldm_x4_t(bl[nf2], svl + so);
            }
#pragma unroll
            for (int mf = 0; mf < 4; ++mf)
#pragma unroll
                for (int nf = 0; nf < 4; ++nf)
                    mma3(acc[mf][nf], ah[mf], al[mf],
                         bh[nf >> 1][(nf & 1) * 2], bh[nf >> 1][(nf & 1) * 2 + 1],
                         bl[nf >> 1][(nf & 1) * 2], bl[nf >> 1][(nf & 1) * 2 + 1]);
        }
    }

    const int r0 = lane >> 2;
    const int c0 = (lane & 3) * 2;
#pragma unroll
    for (int mf = 0; mf < 4; ++mf)
#pragma unroll
        for (int nf = 0; nf < 4; ++nf) {
            int row = wm * 64 + mf * 16 + r0;
            int col = wn * 32 + nf * 8 + c0;
            float2 v0 = {acc[mf][nf][0], acc[mf][nf][1]};
            float2 v1 = {acc[mf][nf][2], acc[mf][nf][3]};
            *reinterpret_cast<float2*>(&ap[(size_t)row * HN + col])       = v0;
            *reinterpret_cast<float2*>(&ap[(size_t)(row + 8) * HN + col]) = v1;
        }
}

// ===========================================================================
// Kernel 3: prefix scan; emits bf16 hi/lo of S.
// ===========================================================================
__global__ void scan_kernel()
{
    int idx = blockIdx.x * blockDim.x + threadIdx.x;
    if (idx >= BN * HN * HN) return;
    int b = idx / (HN * HN);
    int e = idx % (HN * HN);
    const float gL = powf(GAMMA, (float)LN);
    float S = 0.0f;
    for (int c = 0; c < NCN; ++c) {
        size_t off = (size_t)(b * NCN + c) * HN * HN + e;
        __nv_bfloat16 hi = __float2bfloat16_rn(S);
        g_Sh[off] = hi;
        g_Sl[off] = __float2bfloat16_rn(S - __bfloat162float(hi));
        S = fmaf(S, gL, g_A[off]);
    }
}

// ===========================================================================
// Kernel 4: out via mma.  Per chunk:
//   P = Q Kt (masked, decayed)  ->  smem bf16 split
//   O = gamma^i * (Q @ S) + P @ V
// grid (NC, B), 256 thr, warp grid 2x4.
// ===========================================================================
#define OP_HI 0
#define OP_LO 32768
#define OSA   65536      // A stripes: hi at OSA, lo at OSA+8192  [128][32]
#define OSB   81920      // B stripes: hi at OSB, lo at OSB+8192  (either shape)
#define OUT_SMEM 98304

__global__ __launch_bounds__(256) void out_mma(float* __restrict__ out)
{
    extern __shared__ char sm[];
    __shared__ float gp[128];
    const uint32_t sb = smem_u32(sm);

    const int c = blockIdx.x;
    const int b = blockIdx.y;
    const size_t rowbase = (size_t)(b * TN + c * LN);
    const __nv_bfloat16* __restrict__ qh = g_qh + rowbase * HN;
    const __nv_bfloat16* __restrict__ ql = g_ql + rowbase * HN;
    const __nv_bfloat16* __restrict__ kh = g_kh + rowbase * HN;
    const __nv_bfloat16* __restrict__ kl = g_kl + rowbase * HN;
    const __nv_bfloat16* __restrict__ vh = g_vh + rowbase * HN;
    const __nv_bfloat16* __restrict__ vl = g_vl + rowbase * HN;
    const __nv_bfloat16* __restrict__ Sh = g_Sh + (size_t)(b * NCN + c) * HN * HN;
    const __nv_bfloat16* __restrict__ Sl = g_Sl + (size_t)(b * NCN + c) * HN * HN;

    const int tid  = threadIdx.x;
    const int wid  = tid >> 5;
    const int lane = tid & 31;
    const int wm   = wid & 1;
    const int wn   = wid >> 1;

    if (tid < 128) gp[tid] = powf(GAMMA, (float)tid);
    __syncthreads();

    // -------- copy helpers (inline lambdas) --------------------------------
    auto copy128x32 = [&](int dstOff, const __nv_bfloat16* src, int h0) {
#pragma unroll
        for (int r = 0; r < 2; ++r) {
            int id  = tid + 256 * r;
            int row = id >> 2;
            int ch  = id & 3;
            uint4 d = *reinterpret_cast<const uint4*>(&src[(size_t)row * HN + h0 + ch * 8]);
            *reinterpret_cast<uint4*>(sm + dstOff + row * 64 +
                                      ((ch ^ ((row >> 1) & 3)) * 16)) = d;
        }
    };
    auto copy32x128 = [&](int dstOff, const __nv_bfloat16* src) {
#pragma unroll
        for (int r = 0; r < 2; ++r) {
            int id  = tid + 256 * r;
            int row = id >> 4;
            int ch  = id & 15;
            uint4 d = *reinterpret_cast<const uint4*>(&src[(size_t)row * HN + ch * 8]);
            *reinterpret_cast<uint4*>(sm + dstOff + row * 256 +
                                      ((ch ^ (row & 7)) * 16)) = d;
        }
    };

    // ---------------- phase 1: P = Q @ K^T ---------------------------------
    float pAcc[4][4][4];
#pragma unroll
    for (int a = 0; a < 4; ++a)
#pragma unroll
        for (int e = 0; e < 4; ++e)
#pragma unroll
            for (int f = 0; f < 4; ++f) pAcc[a][e][f] = 0.0f;

    const bool p1skip = (wm == 0 && wn >= 2);   // upper triangle, all-masked
    for (int ks = 0; ks < 4; ++ks) {
        __syncthreads();
        copy128x32(OSA,        qh, ks * 32);
        copy128x32(OSA + 8192, ql, ks * 32);
        copy128x32(OSB,        kh, ks * 32);
        copy128x32(OSB + 8192, kl, ks * 32);
        __syncthreads();
        if (p1skip) continue;
#pragma unroll
        for (int kk = 0; kk < 2; ++kk) {
            uint32_t ah[4][4], al[4][4];
            const int arow = lane & 15;
            const int ach  = kk * 2 + (lane >> 4);
#pragma unroll
            for (int mf = 0; mf < 4; ++mf) {
                int row = wm * 64 + mf * 16 + arow;
                uint32_t so = (uint32_t)(row * 64 + ((ach ^ ((row >> 1) & 3)) * 16));
                ldm_x4(ah[mf], sb + OSA + so);
                ldm_x4(al[mf], sb + OSA + 8192 + so);
            }
            uint32_t bh[2][4], bl[2][4];
            const int brow = (lane & 7) + ((lane >> 4) & 1) * 8;
            const int bch  = kk * 2 + ((lane >> 3) & 1);
#pragma unroll
            for (int nf2 = 0; nf2 < 2; ++nf2) {
                int row = wn * 32 + nf2 * 16 + brow;
                uint32_t so = (uint32_t)(row * 64 + ((bch ^ ((row >> 1) & 3)) * 16));
                ldm_x4(bh[nf2], sb + OSB + so);
                ldm_x4(bl[nf2], sb + OSB + 8192 + so);
            }
#pragma unroll
            for (int mf = 0; mf < 4; ++mf)
#pragma unroll
                for (int nf = 0; nf < 4; ++nf)
                    mma3(pAcc[mf][nf], ah[mf], al[mf],
                         bh[nf >> 1][(nf & 1) * 2], bh[nf >> 1][(nf & 1) * 2 + 1],
                         bl[nf >> 1][(nf & 1) * 2], bl[nf >> 1][(nf & 1) * 2 + 1]);
        }
    }

    // ---------------- mask + split + store P to smem -----------------------
    {
        const int r0 = lane >> 2;
        const int c0 = (lane & 3) * 2;
#pragma unroll
        for (int mf = 0; mf < 4; ++mf) {
#pragma unroll
            for (int nf = 0; nf < 4; ++nf) {
                int i0 = wm * 64 + mf * 16 + r0;
                int i1 = i0 + 8;
                int j0 = wn * 32 + nf * 8 + c0;
                int j1 = j0 + 1;
                float d0 = (i0 >= j0) ? pAcc[mf][nf][0] * gp[i0 - j0] : 0.0f;
                float d1 = (i0 >= j1) ? pAcc[mf][nf][1] * gp[i0 - j1] : 0.0f;
                float d2 = (i1 >= j0) ? pAcc[mf][nf][2] * gp[i1 - j0] : 0.0f;
                float d3 = (i1 >= j1) ? pAcc[mf][nf][3] * gp[i1 - j1] : 0.0f;
                uint32_t h0, l0, h1, l1;
                split_pair(d0, d1, h0, l0);
                split_pair(d2, d3, h1, l1);
                uint32_t a0 = (uint32_t)(i0 * 256 + (((j0 >> 3) ^ (i0 & 7)) * 16) + (j0 & 7) * 2);
                uint32_t a1 = (uint32_t)(i1 * 256 + (((j0 >> 3) ^ (i1 & 7)) * 16) + (j0 & 7) * 2);
                *reinterpret_cast<uint32_t*>(sm + OP_HI + a0) = h0;
                *reinterpret_cast<uint32_t*>(sm + OP_LO + a0) = l0;
                *reinterpret_cast<uint32_t*>(sm + OP_HI + a1) = h1;
                *reinterpret_cast<uint32_t*>(sm + OP_LO + a1) = l1;
            }
        }
    }

    // ---------------- phase 2b: O = Q @ S ----------------------------------
    float oAcc[4][4][4];
#pragma unroll
    for (int a = 0; a < 4; ++a)
#pragma unroll
        for (int e = 0; e < 4; ++e)
#pragma unroll
            for (int f = 0; f < 4; ++f) oAcc[a][e][f] = 0.0f;

    for (int ks = 0; ks < 4; ++ks) {
        __syncthreads();
        copy128x32(OSA,        qh, ks * 32);
        copy128x32(OSA + 8192, ql, ks * 32);
        copy32x128(OSB,        Sh + (size_t)ks * 32 * HN);
        copy32x128(OSB + 8192, Sl + (size_t)ks * 32 * HN);
        __syncthreads();
#pragma unroll
        for (int kk = 0; kk < 2; ++kk) {
            uint32_t ah[4][4], al[4][4];
            const int arow = lane & 15;
            const int ach  = kk * 2 + (lane >> 4);
#pragma unroll
            for (int mf = 0; mf < 4; ++mf) {
                int row = wm * 64 + mf * 16 + arow;
                uint32_t so = (uint32_t)(row * 64 + ((ach ^ ((row >> 1) & 3)) * 16));
                ldm_x4(ah[mf], sb + OSA + so);
                ldm_x4(al[mf], sb + OSA + 8192 + so);
            }
            uint32_t bh[2][4], bl[2][4];
            const int brow = kk * 16 + (lane & 7) + ((lane >> 3) & 1) * 8;
#pragma unroll
            for (int nf2 = 0; nf2 < 2; ++nf2) {
                int bch = wn * 4 + nf2 * 2 + ((lane >> 4) & 1);
                uint32_t so = (uint32_t)(brow * 256 + ((bch ^ (brow & 7)) * 16));
                ldm_x4_t(bh[nf2], sb + OSB + so);
                ldm_x4_t(bl[nf2], sb + OSB + 8192 + so);
            }
#pragma unroll
            for (int mf = 0; mf < 4; ++mf)
#pragma unroll
                for (int nf = 0; nf < 4; ++nf)
                    mma3(oAcc[mf][nf], ah[mf], al[mf],
                         bh[nf >> 1][(nf & 1) * 2], bh[nf >> 1][(nf & 1) * 2 + 1],
                         bl[nf >> 1][(nf & 1) * 2], bl[nf >> 1][(nf & 1) * 2 + 1]);
        }
    }
    // scale by gamma^i
    {
        const int r0 = lane >> 2;
#pragma unroll
        for (int mf = 0; mf < 4; ++mf) {
            int i0 = wm * 64 + mf * 16 + r0;
            float f0 = gp[i0], f1 = gp[i0 + 8];
#pragma unroll
            for (int nf = 0; nf < 4; ++nf) {
                oAcc[mf][nf][0] *= f0;
                oAcc[mf][nf][1] *= f0;
                oAcc[mf][nf][2] *= f1;
                oAcc[mf][nf][3] *= f1;
            }
        }
    }

    // ---------------- phase 2a: O += P @ V ---------------------------------
    for (int jt = 0; jt < 4; ++jt) {
        __syncthreads();
        copy32x128(OSB,        vh + (size_t)jt * 32 * HN);
        copy32x128(OSB + 8192, vl + (size_t)jt * 32 * HN);
        __syncthreads();
        if (wm == 0 && jt >= 2) continue;   // P rows < 64 never see j >= 64
#pragma unroll
        for (int kk = 0; kk < 2; ++kk) {
            const int ks = jt * 2 + kk;
            uint32_t ah[4][4], al[4][4];
            const int arow = lane & 15;
            const int ach  = ks * 2 + (lane >> 4);
#pragma unroll
            for (int mf = 0; mf < 4; ++mf) {
                int row = wm * 64 + mf * 16 + arow;
                uint32_t so = (uint32_t)(row * 256 + ((ach ^ (row & 7)) * 16));
                ldm_x4(ah[mf], sb + OP_HI + so);
                ldm_x4(al[mf], sb + OP_LO + so);
            }
            uint32_t bh[2][4], bl[2][4];
            const int brow = kk * 16 + (lane & 7) + ((lane >> 3) & 1) * 8;
#pragma unroll
            for (int nf2 = 0; nf2 < 2; ++nf2) {
                int bch = wn * 4 + nf2 * 2 + ((lane >> 4) & 1);
                uint32_t so = (uint32_t)(brow * 256 + ((bch ^ (brow & 7)) * 16));
                ldm_x4_t(bh[nf2], sb + OSB + so);
                ldm_x4_t(bl[nf2], sb + OSB + 8192 + so);
            }
#pragma unroll
            for (int mf = 0; mf < 4; ++mf)
#pragma unroll
                for (int nf = 0; nf < 4; ++nf)
                    mma3(oAcc[mf][nf], ah[mf], al[mf],
                         bh[nf >> 1][(nf & 1) * 2], bh[nf >> 1][(nf & 1) * 2 + 1],
                         bl[nf >> 1][(nf & 1) * 2], bl[nf >> 1][(nf & 1) * 2 + 1]);
        }
    }

    // ---------------- store O ----------------------------------------------
    {
        const int r0 = lane >> 2;
        const int c0 = (lane & 3) * 2;
#pragma unroll
        for (int mf = 0; mf < 4; ++mf)
#pragma unroll
            for (int nf = 0; nf < 4; ++nf) {
                size_t row = rowbase + wm * 64 + mf * 16 + r0;
                int col = wn * 32 + nf * 8 + c0;
                float2 v0 = {oAcc[mf][nf][0], oAcc[mf][nf][1]};
                float2 v1 = {oAcc[mf][nf][2], oAcc[mf][nf][3]};
                *reinterpret_cast<float2*>(&out[row * HN + col])       = v0;
                *reinterpret_cast<float2*>(&out[(row + 8) * HN + col]) = v1;
            }
    }
}

// ===========================================================================
extern "C" void kernel_launch(void* const* d_in, const int* in_sizes, int n_in,
                              void* d_out, int out_size)
{
    const float* x  = (const float*)d_in[0];
    const float* Wq = (const float*)d_in[1];
    const float* Wk = (const float*)d_in[2];
    const float* Wv = (const float*)d_in[3];
    float* out = (float*)d_out;

    cudaFuncSetAttribute(proj_mma_kernel, cudaFuncAttributeMaxDynamicSharedMemorySize,
                         2 * BUF_SZ);
    cudaFuncSetAttribute(out_mma, cudaFuncAttributeMaxDynamicSharedMemorySize,
                         OUT_SMEM);

    xprep_kernel<<<(MN * CN / 8) / 256, 256>>>(x);
    wprep_kernel<<<dim3(CN, 3), HN>>>(Wq, Wk, Wv);
    proj_mma_kernel<<<dim3(MN / 128, 3), 256, 2 * BUF_SZ>>>();
    chunkkv_mma<<<dim3(NCN, BN), 256>>>();
    scan_kernel<<<(BN * HN * HN + 255) / 256, 256>>>();
    out_mma<<<dim3(NCN, BN), 256, OUT_SMEM>>>(out);
}

// round 6
// speedup vs baseline: 2.8977x; 1.2007x over previous
#include <cuda_runtime.h>
#include <cuda_bf16.h>
#include <math.h>
#include <stdint.h>

// Problem constants: RetentionHead  B=4, T=4096, C=1024, H=128
#define BN 4
#define TN 4096
#define CN 1024
#define HN 128
#define LN 128
#define NCN (TN / LN)          // 32 chunks per batch
#define MN (BN * TN)           // 16384 rows
#define NPROJ 384
#define GAMMA 0.96875f
#define SCALE 0.03125f         // C^-0.5

typedef unsigned long long ull;

// ---------------- mma.sync / ldmatrix / cp.async helpers -------------------
__device__ __forceinline__ uint32_t smem_u32(const void* p) {
    uint32_t a;
    asm("{ .reg .u64 t; cvta.to.shared.u64 t, %1; cvt.u32.u64 %0, t; }" : "=r"(a) : "l"(p));
    return a;
}
__device__ __forceinline__ void cp16(uint32_t s, const void* g) {
    asm volatile("cp.async.cg.shared.global [%0], [%1], 16;" :: "r"(s), "l"(g));
}
__device__ __forceinline__ void cp_commit() {
    asm volatile("cp.async.commit_group;" ::: "memory");
}
__device__ __forceinline__ void ldm_x4(uint32_t* r, uint32_t addr) {
    asm volatile("ldmatrix.sync.aligned.m8n8.x4.shared.b16 {%0,%1,%2,%3}, [%4];"
                 : "=r"(r[0]), "=r"(r[1]), "=r"(r[2]), "=r"(r[3]) : "r"(addr));
}
__device__ __forceinline__ void ldm_x4_t(uint32_t* r, uint32_t addr) {
    asm volatile("ldmatrix.sync.aligned.m8n8.x4.trans.shared.b16 {%0,%1,%2,%3}, [%4];"
                 : "=r"(r[0]), "=r"(r[1]), "=r"(r[2]), "=r"(r[3]) : "r"(addr));
}
__device__ __forceinline__ void mma_bf16(float* d, const uint32_t* a,
                                         uint32_t b0, uint32_t b1) {
    asm volatile(
        "mma.sync.aligned.m16n8k16.row.col.f32.bf16.bf16.f32 "
        "{%0,%1,%2,%3}, {%4,%5,%6,%7}, {%8,%9}, {%0,%1,%2,%3};"
        : "+f"(d[0]), "+f"(d[1]), "+f"(d[2]), "+f"(d[3])
        : "r"(a[0]), "r"(a[1]), "r"(a[2]), "r"(a[3]), "r"(b0), "r"(b1));
}
// 3-product split-2 mma: hi*hi + lo*hi + hi*lo
__device__ __forceinline__ void mma3(float* d, const uint32_t* ah, const uint32_t* al,
                                     uint32_t bh0, uint32_t bh1,
                                     uint32_t bl0, uint32_t bl1) {
    mma_bf16(d, ah, bh0, bh1);
    mma_bf16(d, al, bh0, bh1);
    mma_bf16(d, ah, bl0, bl1);
}
__device__ __forceinline__ uint32_t pack_bf2(float a, float b) {
    __nv_bfloat162 t = __floats2bfloat162_rn(a, b);
    return *reinterpret_cast<uint32_t*>(&t);
}
__device__ __forceinline__ void split_pair(float a, float b, uint32_t& hi, uint32_t& lo) {
    __nv_bfloat16 ah = __float2bfloat16_rn(a);
    __nv_bfloat16 bh = __float2bfloat16_rn(b);
    __nv_bfloat162 hh; hh.x = ah; hh.y = bh;
    hi = *reinterpret_cast<uint32_t*>(&hh);
    lo = pack_bf2(a - __bfloat162float(ah), b - __bfloat162float(bh));
}
__device__ __forceinline__ float bf2sum(uint32_t hw, uint32_t lw, int half) {
    __nv_bfloat162 h = *reinterpret_cast<__nv_bfloat162*>(&hw);
    __nv_bfloat162 l = *reinterpret_cast<__nv_bfloat162*>(&lw);
    return half ? (__bfloat162float(h.y) + __bfloat162float(l.y))
                : (__bfloat162float(h.x) + __bfloat162float(l.x));
}

// ---------------- scratch (device globals) ---------------------------------
__device__ float g_A[BN * NCN * HN * HN];
__device__ __nv_bfloat16 g_qh[MN * HN], g_ql[MN * HN];
__device__ __nv_bfloat16 g_kh[MN * HN], g_kl[MN * HN];
__device__ __nv_bfloat16 g_vh[MN * HN], g_vl[MN * HN];
__device__ __nv_bfloat16 g_Sh[BN * NCN * HN * HN], g_Sl[BN * NCN * HN * HN];
__device__ __nv_bfloat16 g_wt_hi[NPROJ * CN];
__device__ __nv_bfloat16 g_wt_lo[NPROJ * CN];

// ===========================================================================
// Kernel 0: W prep — transpose + split fp32 W[k][n] -> bf16 hi/lo [mat*128+n][k]
// ===========================================================================
__global__ void wprep_kernel(const float* __restrict__ Wq,
                             const float* __restrict__ Wk,
                             const float* __restrict__ Wv)
{
    int k = blockIdx.x;
    int mat = blockIdx.y;
    int n = threadIdx.x;
    const float* W = (mat == 0) ? Wq : (mat == 1) ? Wk : Wv;
    float w = W[(size_t)k * HN + n];
    __nv_bfloat16 hi = __float2bfloat16_rn(w);
    size_t off = ((size_t)mat * HN + n) * CN + k;
    g_wt_hi[off] = hi;
    g_wt_lo[off] = __float2bfloat16_rn(w - __bfloat162float(hi));
}

// ===========================================================================
// Kernel 1: projection GEMM via mma.sync bf16 split-2, fp32 x split fused.
// grid (3, 128): blockIdx.x = mat (adjacent blocks share the x tile via L2),
// blockIdx.y = 128-row M tile.  A: LDG fp32 -> register split -> STS bf16,
// double-buffered with one sync per iter.  B: cp.async double-buffered.
// ===========================================================================
#define OFF_A_HI 0
#define OFF_A_LO 8192
#define OFF_B_HI 16384
#define OFF_B_LO 24576
#define BUF_SZ 32768
#define NKSTEP (CN / 32)

__global__ __launch_bounds__(256) void proj_mma_kernel(const float* __restrict__ x)
{
    extern __shared__ char sm[];
    const uint32_t sbase = smem_u32(sm);
    const int tid  = threadIdx.x;
    const int wid  = tid >> 5;
    const int lane = tid & 31;
    const int wm   = wid & 1;
    const int wn   = wid >> 1;
    const int mat  = blockIdx.x;
    const int m0   = blockIdx.y * 128;
    const int n0   = mat * 128;

    // per-thread tile coords: 512 (row, 16B-bf16-chunk) pairs, 2 per thread
    const int arow0 = tid >> 2;         // +64 for r=1
    const int ach0  = tid & 3;          // chunk of 8 elems

    float acc[4][4][4];
#pragma unroll
    for (int a = 0; a < 4; ++a)
#pragma unroll
        for (int b = 0; b < 4; ++b)
#pragma unroll
            for (int c = 0; c < 4; ++c) acc[a][b][c] = 0.0f;

    // ---- prologue: LDG A(0), cp.async B(0) --------------------------------
    float4 apre[2][2];
#pragma unroll
    for (int r = 0; r < 2; ++r) {
        int row = arow0 + 64 * r;
        const float* src = &x[(size_t)(m0 + row) * CN + ach0 * 8];
        apre[r][0] = *reinterpret_cast<const float4*>(src);
        apre[r][1] = *reinterpret_cast<const float4*>(src + 4);
    }
#pragma unroll
    for (int r = 0; r < 2; ++r) {
        int row = arow0 + 64 * r;
        uint32_t so = (uint32_t)(row * 64 + ((ach0 ^ ((row >> 1) & 3)) * 16));
        cp16(sbase + OFF_B_HI + so, &g_wt_hi[(size_t)(n0 + row) * CN + ach0 * 8]);
        cp16(sbase + OFF_B_LO + so, &g_wt_lo[(size_t)(n0 + row) * CN + ach0 * 8]);
    }
    cp_commit();

    for (int ks = 0; ks < NKSTEP; ++ks) {
        const uint32_t sbuf = sbase + (uint32_t)(ks & 1) * BUF_SZ;
        // ---- split + store A regs into Abuf[cur] --------------------------
#pragma unroll
        for (int r = 0; r < 2; ++r) {
            int row = arow0 + 64 * r;
            float f[8] = {apre[r][0].x, apre[r][0].y, apre[r][0].z, apre[r][0].w,
                          apre[r][1].x, apre[r][1].y, apre[r][1].z, apre[r][1].w};
            uint4 vh, vl;
            uint32_t* ph = &vh.x;
            uint32_t* pl = &vl.x;
#pragma unroll
            for (int q = 0; q < 4; ++q) split_pair(f[2*q], f[2*q+1], ph[q], pl[q]);
            uint32_t so = (uint32_t)(row * 64 + ((ach0 ^ ((row >> 1) & 3)) * 16));
            *reinterpret_cast<uint4*>(sm + (ks & 1) * BUF_SZ + OFF_A_HI + so) = vh;
            *reinterpret_cast<uint4*>(sm + (ks & 1) * BUF_SZ + OFF_A_LO + so) = vl;
        }
        // ---- prefetch next A (LDG) + B (cp.async) -------------------------
        if (ks + 1 < NKSTEP) {
            const int k0n = (ks + 1) * 32;
            const uint32_t snext = sbase + (uint32_t)((ks + 1) & 1) * BUF_SZ;
#pragma unroll
            for (int r = 0; r < 2; ++r) {
                int row = arow0 + 64 * r;
                const float* src = &x[(size_t)(m0 + row) * CN + k0n + ach0 * 8];
                apre[r][0] = *reinterpret_cast<const float4*>(src);
                apre[r][1] = *reinterpret_cast<const float4*>(src + 4);
            }
#pragma unroll
            for (int r = 0; r < 2; ++r) {
                int row = arow0 + 64 * r;
                uint32_t so = (uint32_t)(row * 64 + ((ach0 ^ ((row >> 1) & 3)) * 16));
                cp16(snext + OFF_B_HI + so, &g_wt_hi[(size_t)(n0 + row) * CN + k0n + ach0 * 8]);
                cp16(snext + OFF_B_LO + so, &g_wt_lo[(size_t)(n0 + row) * CN + k0n + ach0 * 8]);
            }
            cp_commit();
            asm volatile("cp.async.wait_group 1;" ::: "memory");
        } else {
            asm volatile("cp.async.wait_group 0;" ::: "memory");
        }
        __syncthreads();

        // ---- mma on Abuf[cur] / Bbuf[cur] ---------------------------------
#pragma unroll
        for (int kk = 0; kk < 2; ++kk) {
            uint32_t ah[4][4], al[4][4];
            const int arow = lane & 15;
            const int ach  = kk * 2 + (lane >> 4);
#pragma unroll
            for (int mf = 0; mf < 4; ++mf) {
                int row = wm * 64 + mf * 16 + arow;
                uint32_t so = (uint32_t)(row * 64 + ((ach ^ ((row >> 1) & 3)) * 16));
                ldm_x4(ah[mf], sbuf + OFF_A_HI + so);
                ldm_x4(al[mf], sbuf + OFF_A_LO + so);
            }
            uint32_t bh[2][4], bl[2][4];
            const int brow = (lane & 7) + ((lane >> 4) & 1) * 8;
            const int bch  = kk * 2 + ((lane >> 3) & 1);
#pragma unroll
            for (int nf2 = 0; nf2 < 2; ++nf2) {
                int row = wn * 32 + nf2 * 16 + brow;
                uint32_t so = (uint32_t)(row * 64 + ((bch ^ ((row >> 1) & 3)) * 16));
                ldm_x4(bh[nf2], sbuf + OFF_B_HI + so);
                ldm_x4(bl[nf2], sbuf + OFF_B_LO + so);
            }
#pragma unroll
            for (int mf = 0; mf < 4; ++mf)
#pragma unroll
                for (int nf = 0; nf < 4; ++nf)
                    mma3(acc[mf][nf], ah[mf], al[mf],
                         bh[nf >> 1][(nf & 1) * 2], bh[nf >> 1][(nf & 1) * 2 + 1],
                         bl[nf >> 1][(nf & 1) * 2], bl[nf >> 1][(nf & 1) * 2 + 1]);
        }
        __syncthreads();
    }

    // ---- epilogue: write bf16 splits of q (scaled) / k / v ----------------
    const float sc = (mat == 0) ? SCALE : 1.0f;
    __nv_bfloat16* dsth = (mat == 0) ? g_qh : (mat == 1) ? g_kh : g_vh;
    __nv_bfloat16* dstl = (mat == 0) ? g_ql : (mat == 1) ? g_kl : g_vl;
    const int r0 = lane >> 2;
    const int c0 = (lane & 3) * 2;
#pragma unroll
    for (int mf = 0; mf < 4; ++mf) {
#pragma unroll
        for (int nf = 0; nf < 4; ++nf) {
            int row = m0 + wm * 64 + mf * 16 + r0;
            int col = wn * 32 + nf * 8 + c0;
            float d0 = acc[mf][nf][0] * sc, d1 = acc[mf][nf][1] * sc;
            float d2 = acc[mf][nf][2] * sc, d3 = acc[mf][nf][3] * sc;
            uint32_t h0, l0, h1, l1;
            split_pair(d0, d1, h0, l0);
            split_pair(d2, d3, h1, l1);
            *reinterpret_cast<uint32_t*>(&dsth[(size_t)row * HN + col])       = h0;
            *reinterpret_cast<uint32_t*>(&dstl[(size_t)row * HN + col])       = l0;
            *reinterpret_cast<uint32_t*>(&dsth[(size_t)(row + 8) * HN + col]) = h1;
            *reinterpret_cast<uint32_t*>(&dstl[(size_t)(row + 8) * HN + col]) = l1;
        }
    }
}

// ===========================================================================
// Kernel 2: chunkkv via mma.  A_c[hk][hv] = sum_j g^(L-j) k[j,hk] v[j,hv]
// k reconstructed from bf16 splits (kh+kl), decayed, re-split at runtime.
// ===========================================================================
__global__ __launch_bounds__(256) void chunkkv_mma()
{
    __shared__ __align__(16) char KHI[8192], KLO[8192], VHI[8192], VLO[8192];
    __shared__ float gp[132];

    const int c = blockIdx.x;
    const int b = blockIdx.y;
    const size_t rowbase = (size_t)(b * TN + c * LN);
    const __nv_bfloat16* __restrict__ khp = g_kh + rowbase * HN;
    const __nv_bfloat16* __restrict__ klp = g_kl + rowbase * HN;
    const __nv_bfloat16* __restrict__ vhp = g_vh + rowbase * HN;
    const __nv_bfloat16* __restrict__ vlp = g_vl + rowbase * HN;
    float* __restrict__ ap = g_A + (size_t)(b * NCN + c) * HN * HN;

    const int tid  = threadIdx.x;
    const int wid  = tid >> 5;
    const int lane = tid & 31;
    const int wm   = wid & 1;
    const int wn   = wid >> 1;

    if (tid < 132) gp[tid] = powf(GAMMA, (float)tid);
    const uint32_t skh = smem_u32(KHI), skl = smem_u32(KLO);
    const uint32_t svh = smem_u32(VHI), svl = smem_u32(VLO);
    __syncthreads();

    float acc[4][4][4];
#pragma unroll
    for (int a = 0; a < 4; ++a)
#pragma unroll
        for (int e = 0; e < 4; ++e)
#pragma unroll
            for (int f = 0; f < 4; ++f) acc[a][e][f] = 0.0f;

    for (int jt = 0; jt < 4; ++jt) {
        __syncthreads();
        // decayed k split stripe [32 j][128 hk]
#pragma unroll
        for (int r = 0; r < 2; ++r) {
            int id  = tid + 256 * r;
            int row = id >> 4;
            int ch  = id & 15;
            int j   = jt * 32 + row;
            float w = gp[LN - j];
            uint4 dh = *reinterpret_cast<const uint4*>(&khp[(size_t)j * HN + ch * 8]);
            uint4 dl = *reinterpret_cast<const uint4*>(&klp[(size_t)j * HN + ch * 8]);
            const uint32_t* hw = &dh.x;
            const uint32_t* lw = &dl.x;
            uint4 vh4, vl4;
            uint32_t* ph = &vh4.x;
            uint32_t* pl = &vl4.x;
#pragma unroll
            for (int q = 0; q < 4; ++q) {
                float f0 = bf2sum(hw[q], lw[q], 0) * w;
                float f1 = bf2sum(hw[q], lw[q], 1) * w;
                split_pair(f0, f1, ph[q], pl[q]);
            }
            uint32_t dst = (uint32_t)(row * 256 + ((ch ^ (row & 7)) * 16));
            *reinterpret_cast<uint4*>(KHI + dst) = vh4;
            *reinterpret_cast<uint4*>(KLO + dst) = vl4;
        }
        // v split stripe [32 j][128 hv]
#pragma unroll
        for (int r = 0; r < 2; ++r) {
            int id  = tid + 256 * r;
            int row = id >> 4;
            int ch  = id & 15;
            int j   = jt * 32 + row;
            uint4 dh = *reinterpret_cast<const uint4*>(&vhp[(size_t)j * HN + ch * 8]);
            uint4 dl = *reinterpret_cast<const uint4*>(&vlp[(size_t)j * HN + ch * 8]);
            uint32_t dst = (uint32_t)(row * 256 + ((ch ^ (row & 7)) * 16));
            *reinterpret_cast<uint4*>(VHI + dst) = dh;
            *reinterpret_cast<uint4*>(VLO + dst) = dl;
        }
        __syncthreads();

#pragma unroll
        for (int kk = 0; kk < 2; ++kk) {
            uint32_t ah[4][4], al[4][4];
            const int arow = kk * 16 + (lane & 7) + ((lane >> 4) & 1) * 8;
#pragma unroll
            for (int mf = 0; mf < 4; ++mf) {
                int ach = wm * 8 + mf * 2 + ((lane >> 3) & 1);
                uint32_t so = (uint32_t)(arow * 256 + ((ach ^ (arow & 7)) * 16));
                ldm_x4_t(ah[mf], skh + so);
                ldm_x4_t(al[mf], skl + so);
            }
            uint32_t bh[2][4], bl[2][4];
            const int brow = kk * 16 + (lane & 7) + ((lane >> 3) & 1) * 8;
#pragma unroll
            for (int nf2 = 0; nf2 < 2; ++nf2) {
                int bch = wn * 4 + nf2 * 2 + ((lane >> 4) & 1);
                uint32_t so = (uint32_t)(brow * 256 + ((bch ^ (brow & 7)) * 16));
                ldm_x4_t(bh[nf2], svh + so);
                ldm_x4_t(bl[nf2], svl + so);
            }
#pragma unroll
            for (int mf = 0; mf < 4; ++mf)
#pragma unroll
                for (int nf = 0; nf < 4; ++nf)
                    mma3(acc[mf][nf], ah[mf], al[mf],
                         bh[nf >> 1][(nf & 1) * 2], bh[nf >> 1][(nf & 1) * 2 + 1],
                         bl[nf >> 1][(nf & 1) * 2], bl[nf >> 1][(nf & 1) * 2 + 1]);
        }
    }

    const int r0 = lane >> 2;
    const int c0 = (lane & 3) * 2;
#pragma unroll
    for (int mf = 0; mf < 4; ++mf)
#pragma unroll
        for (int nf = 0; nf < 4; ++nf) {
            int row = wm * 64 + mf * 16 + r0;
            int col = wn * 32 + nf * 8 + c0;
            float2 v0 = {acc[mf][nf][0], acc[mf][nf][1]};
            float2 v1 = {acc[mf][nf][2], acc[mf][nf][3]};
            *reinterpret_cast<float2*>(&ap[(size_t)row * HN + col])       = v0;
            *reinterpret_cast<float2*>(&ap[(size_t)(row + 8) * HN + col]) = v1;
        }
}

// ===========================================================================
// Kernel 3: prefix scan; emits bf16 hi/lo of S.
// ===========================================================================
__global__ void scan_kernel()
{
    int idx = blockIdx.x * blockDim.x + threadIdx.x;
    if (idx >= BN * HN * HN) return;
    int b = idx / (HN * HN);
    int e = idx % (HN * HN);
    const float gL = powf(GAMMA, (float)LN);
    float S = 0.0f;
    for (int c = 0; c < NCN; ++c) {
        size_t off = (size_t)(b * NCN + c) * HN * HN + e;
        __nv_bfloat16 hi = __float2bfloat16_rn(S);
        g_Sh[off] = hi;
        g_Sl[off] = __float2bfloat16_rn(S - __bfloat162float(hi));
        S = fmaf(S, gL, g_A[off]);
    }
}

// ===========================================================================
// Kernel 4: out via mma (unchanged from R5)
// ===========================================================================
#define OP_HI 0
#define OP_LO 32768
#define OSA   65536
#define OSB   81920
#define OUT_SMEM 98304

__global__ __launch_bounds__(256) void out_mma(float* __restrict__ out)
{
    extern __shared__ char sm[];
    __shared__ float gp[128];
    const uint32_t sb = smem_u32(sm);

    const int c = blockIdx.x;
    const int b = blockIdx.y;
    const size_t rowbase = (size_t)(b * TN + c * LN);
    const __nv_bfloat16* __restrict__ qh = g_qh + rowbase * HN;
    const __nv_bfloat16* __restrict__ ql = g_ql + rowbase * HN;
    const __nv_bfloat16* __restrict__ kh = g_kh + rowbase * HN;
    const __nv_bfloat16* __restrict__ kl = g_kl + rowbase * HN;
    const __nv_bfloat16* __restrict__ vh = g_vh + rowbase * HN;
    const __nv_bfloat16* __restrict__ vl = g_vl + rowbase * HN;
    const __nv_bfloat16* __restrict__ Sh = g_Sh + (size_t)(b * NCN + c) * HN * HN;
    const __nv_bfloat16* __restrict__ Sl = g_Sl + (size_t)(b * NCN + c) * HN * HN;

    const int tid  = threadIdx.x;
    const int wid  = tid >> 5;
    const int lane = tid & 31;
    const int wm   = wid & 1;
    const int wn   = wid >> 1;

    if (tid < 128) gp[tid] = powf(GAMMA, (float)tid);
    __syncthreads();

    auto copy128x32 = [&](int dstOff, const __nv_bfloat16* src, int h0) {
#pragma unroll
        for (int r = 0; r < 2; ++r) {
            int id  = tid + 256 * r;
            int row = id >> 2;
            int ch  = id & 3;
            uint4 d = *reinterpret_cast<const uint4*>(&src[(size_t)row * HN + h0 + ch * 8]);
            *reinterpret_cast<uint4*>(sm + dstOff + row * 64 +
                                      ((ch ^ ((row >> 1) & 3)) * 16)) = d;
        }
    };
    auto copy32x128 = [&](int dstOff, const __nv_bfloat16* src) {
#pragma unroll
        for (int r = 0; r < 2; ++r) {
            int id  = tid + 256 * r;
            int row = id >> 4;
            int ch  = id & 15;
            uint4 d = *reinterpret_cast<const uint4*>(&src[(size_t)row * HN + ch * 8]);
            *reinterpret_cast<uint4*>(sm + dstOff + row * 256 +
                                      ((ch ^ (row & 7)) * 16)) = d;
        }
    };

    float pAcc[4][4][4];
#pragma unroll
    for (int a = 0; a < 4; ++a)
#pragma unroll
        for (int e = 0; e < 4; ++e)
#pragma unroll
            for (int f = 0; f < 4; ++f) pAcc[a][e][f] = 0.0f;

    const bool p1skip = (wm == 0 && wn >= 2);
    for (int ks = 0; ks < 4; ++ks) {
        __syncthreads();
        copy128x32(OSA,        qh, ks * 32);
        copy128x32(OSA + 8192, ql, ks * 32);
        copy128x32(OSB,        kh, ks * 32);
        copy128x32(OSB + 8192, kl, ks * 32);
        __syncthreads();
        if (p1skip) continue;
#pragma unroll
        for (int kk = 0; kk < 2; ++kk) {
            uint32_t ah[4][4], al[4][4];
            const int arow = lane & 15;
            const int ach  = kk * 2 + (lane >> 4);
#pragma unroll
            for (int mf = 0; mf < 4; ++mf) {
                int row = wm * 64 + mf * 16 + arow;
                uint32_t so = (uint32_t)(row * 64 + ((ach ^ ((row >> 1) & 3)) * 16));
                ldm_x4(ah[mf], sb + OSA + so);
                ldm_x4(al[mf], sb + OSA + 8192 + so);
            }
            uint32_t bh[2][4], bl[2][4];
            const int brow = (lane & 7) + ((lane >> 4) & 1) * 8;
            const int bch  = kk * 2 + ((lane >> 3) & 1);
#pragma unroll
            for (int nf2 = 0; nf2 < 2; ++nf2) {
                int row = wn * 32 + nf2 * 16 + brow;
                uint32_t so = (uint32_t)(row * 64 + ((bch ^ ((row >> 1) & 3)) * 16));
                ldm_x4(bh[nf2], sb + OSB + so);
                ldm_x4(bl[nf2], sb + OSB + 8192 + so);
            }
#pragma unroll
            for (int mf = 0; mf < 4; ++mf)
#pragma unroll
                for (int nf = 0; nf < 4; ++nf)
                    mma3(pAcc[mf][nf], ah[mf], al[mf],
                         bh[nf >> 1][(nf & 1) * 2], bh[nf >> 1][(nf & 1) * 2 + 1],
                         bl[nf >> 1][(nf & 1) * 2], bl[nf >> 1][(nf & 1) * 2 + 1]);
        }
    }

    {
        const int r0 = lane >> 2;
        const int c0 = (lane & 3) * 2;
#pragma unroll
        for (int mf = 0; mf < 4; ++mf) {
#pragma unroll
            for (int nf = 0; nf < 4; ++nf) {
                int i0 = wm * 64 + mf * 16 + r0;
                int i1 = i0 + 8;
                int j0 = wn * 32 + nf * 8 + c0;
                int j1 = j0 + 1;
                float d0 = (i0 >= j0) ? pAcc[mf][nf][0] * gp[i0 - j0] : 0.0f;
                float d1 = (i0 >= j1) ? pAcc[mf][nf][1] * gp[i0 - j1] : 0.0f;
                float d2 = (i1 >= j0) ? pAcc[mf][nf][2] * gp[i1 - j0] : 0.0f;
                float d3 = (i1 >= j1) ? pAcc[mf][nf][3] * gp[i1 - j1] : 0.0f;
                uint32_t h0, l0, h1, l1;
                split_pair(d0, d1, h0, l0);
                split_pair(d2, d3, h1, l1);
                uint32_t a0 = (uint32_t)(i0 * 256 + (((j0 >> 3) ^ (i0 & 7)) * 16) + (j0 & 7) * 2);
                uint32_t a1 = (uint32_t)(i1 * 256 + (((j0 >> 3) ^ (i1 & 7)) * 16) + (j0 & 7) * 2);
                *reinterpret_cast<uint32_t*>(sm + OP_HI + a0) = h0;
                *reinterpret_cast<uint32_t*>(sm + OP_LO + a0) = l0;
                *reinterpret_cast<uint32_t*>(sm + OP_HI + a1) = h1;
                *reinterpret_cast<uint32_t*>(sm + OP_LO + a1) = l1;
            }
        }
    }

    float oAcc[4][4][4];
#pragma unroll
    for (int a = 0; a < 4; ++a)
#pragma unroll
        for (int e = 0; e < 4; ++e)
#pragma unroll
            for (int f = 0; f < 4; ++f) oAcc[a][e][f] = 0.0f;

    for (int ks = 0; ks < 4; ++ks) {
        __syncthreads();
        copy128x32(OSA,        qh, ks * 32);
        copy128x32(OSA + 8192, ql, ks * 32);
        copy32x128(OSB,        Sh + (size_t)ks * 32 * HN);
        copy32x128(OSB + 8192, Sl + (size_t)ks * 32 * HN);
        __syncthreads();
#pragma unroll
        for (int kk = 0; kk < 2; ++kk) {
            uint32_t ah[4][4], al[4][4];
            const int arow = lane & 15;
            const int ach  = kk * 2 + (lane >> 4);
#pragma unroll
            for (int mf = 0; mf < 4; ++mf) {
                int row = wm * 64 + mf * 16 + arow;
                uint32_t so = (uint32_t)(row * 64 + ((ach ^ ((row >> 1) & 3)) * 16));
                ldm_x4(ah[mf], sb + OSA + so);
                ldm_x4(al[mf], sb + OSA + 8192 + so);
            }
            uint32_t bh[2][4], bl[2][4];
            const int brow = kk * 16 + (lane & 7) + ((lane >> 3) & 1) * 8;
#pragma unroll
            for (int nf2 = 0; nf2 < 2; ++nf2) {
                int bch = wn * 4 + nf2 * 2 + ((lane >> 4) & 1);
                uint32_t so = (uint32_t)(brow * 256 + ((bch ^ (brow & 7)) * 16));
                ldm_x4_t(bh[nf2], sb + OSB + so);
                ldm_x4_t(bl[nf2], sb + OSB + 8192 + so);
            }
#pragma unroll
            for (int mf = 0; mf < 4; ++mf)
#pragma unroll
                for (int nf = 0; nf < 4; ++nf)
                    mma3(oAcc[mf][nf], ah[mf], al[mf],
                         bh[nf >> 1][(nf & 1) * 2], bh[nf >> 1][(nf & 1) * 2 + 1],
                         bl[nf >> 1][(nf & 1) * 2], bl[nf >> 1][(nf & 1) * 2 + 1]);
        }
    }
    {
        const int r0 = lane >> 2;
#pragma unroll
        for (int mf = 0; mf < 4; ++mf) {
            int i0 = wm * 64 + mf * 16 + r0;
            float f0 = gp[i0], f1 = gp[i0 + 8];
#pragma unroll
            for (int nf = 0; nf < 4; ++nf) {
                oAcc[mf][nf][0] *= f0;
                oAcc[mf][nf][1] *= f0;
                oAcc[mf][nf][2] *= f1;
                oAcc[mf][nf][3] *= f1;
            }
        }
    }

    for (int jt = 0; jt < 4; ++jt) {
        __syncthreads();
        copy32x128(OSB,        vh + (size_t)jt * 32 * HN);
        copy32x128(OSB + 8192, vl + (size_t)jt * 32 * HN);
        __syncthreads();
        if (wm == 0 && jt >= 2) continue;
#pragma unroll
        for (int kk = 0; kk < 2; ++kk) {
            const int ks = jt * 2 + kk;
            uint32_t ah[4][4], al[4][4];
            const int arow = lane & 15;
            const int ach  = ks * 2 + (lane >> 4);
#pragma unroll
            for (int mf = 0; mf < 4; ++mf) {
                int row = wm * 64 + mf * 16 + arow;
                uint32_t so = (uint32_t)(row * 256 + ((ach ^ (row & 7)) * 16));
                ldm_x4(ah[mf], sb + OP_HI + so);
                ldm_x4(al[mf], sb + OP_LO + so);
            }
            uint32_t bh[2][4], bl[2][4];
            const int brow = kk * 16 + (lane & 7) + ((lane >> 3) & 1) * 8;
#pragma unroll
            for (int nf2 = 0; nf2 < 2; ++nf2) {
                int bch = wn * 4 + nf2 * 2 + ((lane >> 4) & 1);
                uint32_t so = (uint32_t)(brow * 256 + ((bch ^ (brow & 7)) * 16));
                ldm_x4_t(bh[nf2], sb + OSB + so);
                ldm_x4_t(bl[nf2], sb + OSB + 8192 + so);
            }
#pragma unroll
            for (int mf = 0; mf < 4; ++mf)
#pragma unroll
                for (int nf = 0; nf < 4; ++nf)
                    mma3(oAcc[mf][nf], ah[mf], al[mf],
                         bh[nf >> 1][(nf & 1) * 2], bh[nf >> 1][(nf & 1) * 2 + 1],
                         bl[nf >> 1][(nf & 1) * 2], bl[nf >> 1][(nf & 1) * 2 + 1]);
        }
    }

    {
        const int r0 = lane >> 2;
        const int c0 = (lane & 3) * 2;
#pragma unroll
        for (int mf = 0; mf < 4; ++mf)
#pragma unroll
            for (int nf = 0; nf < 4; ++nf) {
                size_t row = rowbase + wm * 64 + mf * 16 + r0;
                int col = wn * 32 + nf * 8 + c0;
                float2 v0 = {oAcc[mf][nf][0], oAcc[mf][nf][1]};
                float2 v1 = {oAcc[mf][nf][2], oAcc[mf][nf][3]};
                *reinterpret_cast<float2*>(&out[row * HN + col])       = v0;
                *reinterpret_cast<float2*>(&out[(row + 8) * HN + col]) = v1;
            }
    }
}

// ===========================================================================
extern "C" void kernel_launch(void* const* d_in, const int* in_sizes, int n_in,
                              void* d_out, int out_size)
{
    const float* x  = (const float*)d_in[0];
    const float* Wq = (const float*)d_in[1];
    const float* Wk = (const float*)d_in[2];
    const float* Wv = (const float*)d_in[3];
    float* out = (float*)d_out;

    cudaFuncSetAttribute(proj_mma_kernel, cudaFuncAttributeMaxDynamicSharedMemorySize,
                         2 * BUF_SZ);
    cudaFuncSetAttribute(out_mma, cudaFuncAttributeMaxDynamicSharedMemorySize,
                         OUT_SMEM);

    wprep_kernel<<<dim3(CN, 3), HN>>>(Wq, Wk, Wv);
    proj_mma_kernel<<<dim3(3, MN / 128), 256, 2 * BUF_SZ>>>(x);
    chunkkv_mma<<<dim3(NCN, BN), 256>>>();
    scan_kernel<<<(BN * HN * HN + 255) / 256, 256>>>();
    out_mma<<<dim3(NCN, BN), 256, OUT_SMEM>>>(out);
}

// round 9
// speedup vs baseline: 3.0760x; 1.0615x over previous
#include <cuda_runtime.h>
#include <cuda_bf16.h>
#include <math.h>
#include <stdint.h>

// Problem constants: RetentionHead  B=4, T=4096, C=1024, H=128
#define BN 4
#define TN 4096
#define CN 1024
#define HN 128
#define LN 128
#define NCN (TN / LN)          // 32 chunks per batch
#define MN (BN * TN)           // 16384 rows
#define NPROJ 384
#define GAMMA 0.96875f
#define SCALE 0.03125f         // C^-0.5

typedef unsigned long long ull;

// ---------------- mma.sync / ldmatrix / cp.async helpers -------------------
__device__ __forceinline__ uint32_t smem_u32(const void* p) {
    uint32_t a;
    asm("{ .reg .u64 t; cvta.to.shared.u64 t, %1; cvt.u32.u64 %0, t; }" : "=r"(a) : "l"(p));
    return a;
}
__device__ __forceinline__ void cp16(uint32_t s, const void* g) {
    asm volatile("cp.async.cg.shared.global [%0], [%1], 16;" :: "r"(s), "l"(g));
}
__device__ __forceinline__ void cp_commit() {
    asm volatile("cp.async.commit_group;" ::: "memory");
}
__device__ __forceinline__ void ldm_x4(uint32_t* r, uint32_t addr) {
    asm volatile("ldmatrix.sync.aligned.m8n8.x4.shared.b16 {%0,%1,%2,%3}, [%4];"
                 : "=r"(r[0]), "=r"(r[1]), "=r"(r[2]), "=r"(r[3]) : "r"(addr));
}
__device__ __forceinline__ void ldm_x4_t(uint32_t* r, uint32_t addr) {
    asm volatile("ldmatrix.sync.aligned.m8n8.x4.trans.shared.b16 {%0,%1,%2,%3}, [%4];"
                 : "=r"(r[0]), "=r"(r[1]), "=r"(r[2]), "=r"(r[3]) : "r"(addr));
}
__device__ __forceinline__ void mma_bf16(float* d, const uint32_t* a,
                                         uint32_t b0, uint32_t b1) {
    asm volatile(
        "mma.sync.aligned.m16n8k16.row.col.f32.bf16.bf16.f32 "
        "{%0,%1,%2,%3}, {%4,%5,%6,%7}, {%8,%9}, {%0,%1,%2,%3};"
        : "+f"(d[0]), "+f"(d[1]), "+f"(d[2]), "+f"(d[3])
        : "r"(a[0]), "r"(a[1]), "r"(a[2]), "r"(a[3]), "r"(b0), "r"(b1));
}
// 3-product split-2 mma: hi*hi + lo*hi + hi*lo
__device__ __forceinline__ void mma3(float* d, const uint32_t* ah, const uint32_t* al,
                                     uint32_t bh0, uint32_t bh1,
                                     uint32_t bl0, uint32_t bl1) {
    mma_bf16(d, ah, bh0, bh1);
    mma_bf16(d, al, bh0, bh1);
    mma_bf16(d, ah, bl0, bl1);
}
__device__ __forceinline__ uint32_t pack_bf2(float a, float b) {
    __nv_bfloat162 t = __floats2bfloat162_rn(a, b);
    return *reinterpret_cast<uint32_t*>(&t);
}
__device__ __forceinline__ void split_pair(float a, float b, uint32_t& hi, uint32_t& lo) {
    __nv_bfloat16 ah = __float2bfloat16_rn(a);
    __nv_bfloat16 bh = __float2bfloat16_rn(b);
    __nv_bfloat162 hh; hh.x = ah; hh.y = bh;
    hi = *reinterpret_cast<uint32_t*>(&hh);
    lo = pack_bf2(a - __bfloat162float(ah), b - __bfloat162float(bh));
}
__device__ __forceinline__ float bf2sum(uint32_t hw, uint32_t lw, int half) {
    __nv_bfloat162 h = *reinterpret_cast<__nv_bfloat162*>(&hw);
    __nv_bfloat162 l = *reinterpret_cast<__nv_bfloat162*>(&lw);
    return half ? (__bfloat162float(h.y) + __bfloat162float(l.y))
                : (__bfloat162float(h.x) + __bfloat162float(l.x));
}

// ---------------- scratch (device globals) ---------------------------------
__device__ float g_A[BN * NCN * HN * HN];
__device__ __nv_bfloat16 g_qh[MN * HN], g_ql[MN * HN];
__device__ __nv_bfloat16 g_kh[MN * HN], g_kl[MN * HN];
__device__ __nv_bfloat16 g_vh[MN * HN], g_vl[MN * HN];
__device__ __nv_bfloat16 g_Sh[BN * NCN * HN * HN], g_Sl[BN * NCN * HN * HN];
__device__ __nv_bfloat16 g_wt_hi[NPROJ * CN];
__device__ __nv_bfloat16 g_wt_lo[NPROJ * CN];

// ===========================================================================
// Kernel 0: W prep — transpose + split fp32 W[k][n] -> bf16 hi/lo [mat*128+n][k]
// ===========================================================================
__global__ void wprep_kernel(const float* __restrict__ Wq,
                             const float* __restrict__ Wk,
                             const float* __restrict__ Wv)
{
    int k = blockIdx.x;
    int mat = blockIdx.y;
    int n = threadIdx.x;
    const float* W = (mat == 0) ? Wq : (mat == 1) ? Wk : Wv;
    float w = W[(size_t)k * HN + n];
    __nv_bfloat16 hi = __float2bfloat16_rn(w);
    size_t off = ((size_t)mat * HN + n) * CN + k;
    g_wt_hi[off] = hi;
    g_wt_lo[off] = __float2bfloat16_rn(w - __bfloat162float(hi));
}

// ===========================================================================
// Kernel 1: projection GEMM via mma.sync bf16 split-2, fp32 x split fused.
// ===========================================================================
#define OFF_A_HI 0
#define OFF_A_LO 8192
#define OFF_B_HI 16384
#define OFF_B_LO 24576
#define BUF_SZ 32768
#define NKSTEP (CN / 32)

__global__ __launch_bounds__(256) void proj_mma_kernel(const float* __restrict__ x)
{
    extern __shared__ char sm[];
    const uint32_t sbase = smem_u32(sm);
    const int tid  = threadIdx.x;
    const int wid  = tid >> 5;
    const int lane = tid & 31;
    const int wm   = wid & 1;
    const int wn   = wid >> 1;
    const int mat  = blockIdx.x;
    const int m0   = blockIdx.y * 128;
    const int n0   = mat * 128;

    const int arow0 = tid >> 2;
    const int ach0  = tid & 3;

    float acc[4][4][4];
#pragma unroll
    for (int a = 0; a < 4; ++a)
#pragma unroll
        for (int b = 0; b < 4; ++b)
#pragma unroll
            for (int c = 0; c < 4; ++c) acc[a][b][c] = 0.0f;

    float4 apre[2][2];
#pragma unroll
    for (int r = 0; r < 2; ++r) {
        int row = arow0 + 64 * r;
        const float* src = &x[(size_t)(m0 + row) * CN + ach0 * 8];
        apre[r][0] = *reinterpret_cast<const float4*>(src);
        apre[r][1] = *reinterpret_cast<const float4*>(src + 4);
    }
#pragma unroll
    for (int r = 0; r < 2; ++r) {
        int row = arow0 + 64 * r;
        uint32_t so = (uint32_t)(row * 64 + ((ach0 ^ ((row >> 1) & 3)) * 16));
        cp16(sbase + OFF_B_HI + so, &g_wt_hi[(size_t)(n0 + row) * CN + ach0 * 8]);
        cp16(sbase + OFF_B_LO + so, &g_wt_lo[(size_t)(n0 + row) * CN + ach0 * 8]);
    }
    cp_commit();

    for (int ks = 0; ks < NKSTEP; ++ks) {
        const uint32_t sbuf = sbase + (uint32_t)(ks & 1) * BUF_SZ;
#pragma unroll
        for (int r = 0; r < 2; ++r) {
            int row = arow0 + 64 * r;
            float f[8] = {apre[r][0].x, apre[r][0].y, apre[r][0].z, apre[r][0].w,
                          apre[r][1].x, apre[r][1].y, apre[r][1].z, apre[r][1].w};
            uint4 vh, vl;
            uint32_t* ph = &vh.x;
            uint32_t* pl = &vl.x;
#pragma unroll
            for (int q = 0; q < 4; ++q) split_pair(f[2*q], f[2*q+1], ph[q], pl[q]);
            uint32_t so = (uint32_t)(row * 64 + ((ach0 ^ ((row >> 1) & 3)) * 16));
            *reinterpret_cast<uint4*>(sm + (ks & 1) * BUF_SZ + OFF_A_HI + so) = vh;
            *reinterpret_cast<uint4*>(sm + (ks & 1) * BUF_SZ + OFF_A_LO + so) = vl;
        }
        if (ks + 1 < NKSTEP) {
            const int k0n = (ks + 1) * 32;
            const uint32_t snext = sbase + (uint32_t)((ks + 1) & 1) * BUF_SZ;
#pragma unroll
            for (int r = 0; r < 2; ++r) {
                int row = arow0 + 64 * r;
                const float* src = &x[(size_t)(m0 + row) * CN + k0n + ach0 * 8];
                apre[r][0] = *reinterpret_cast<const float4*>(src);
                apre[r][1] = *reinterpret_cast<const float4*>(src + 4);
            }
#pragma unroll
            for (int r = 0; r < 2; ++r) {
                int row = arow0 + 64 * r;
                uint32_t so = (uint32_t)(row * 64 + ((ach0 ^ ((row >> 1) & 3)) * 16));
                cp16(snext + OFF_B_HI + so, &g_wt_hi[(size_t)(n0 + row) * CN + k0n + ach0 * 8]);
                cp16(snext + OFF_B_LO + so, &g_wt_lo[(size_t)(n0 + row) * CN + k0n + ach0 * 8]);
            }
            cp_commit();
            asm volatile("cp.async.wait_group 1;" ::: "memory");
        } else {
            asm volatile("cp.async.wait_group 0;" ::: "memory");
        }
        __syncthreads();

#pragma unroll
        for (int kk = 0; kk < 2; ++kk) {
            uint32_t ah[4][4], al[4][4];
            const int arow = lane & 15;
            const int ach  = kk * 2 + (lane >> 4);
#pragma unroll
            for (int mf = 0; mf < 4; ++mf) {
                int row = wm * 64 + mf * 16 + arow;
                uint32_t so = (uint32_t)(row * 64 + ((ach ^ ((row >> 1) & 3)) * 16));
                ldm_x4(ah[mf], sbuf + OFF_A_HI + so);
                ldm_x4(al[mf], sbuf + OFF_A_LO + so);
            }
            uint32_t bh[2][4], bl[2][4];
            const int brow = (lane & 7) + ((lane >> 4) & 1) * 8;
            const int bch  = kk * 2 + ((lane >> 3) & 1);
#pragma unroll
            for (int nf2 = 0; nf2 < 2; ++nf2) {
                int row = wn * 32 + nf2 * 16 + brow;
                uint32_t so = (uint32_t)(row * 64 + ((bch ^ ((row >> 1) & 3)) * 16));
                ldm_x4(bh[nf2], sbuf + OFF_B_HI + so);
                ldm_x4(bl[nf2], sbuf + OFF_B_LO + so);
            }
#pragma unroll
            for (int mf = 0; mf < 4; ++mf)
#pragma unroll
                for (int nf = 0; nf < 4; ++nf)
                    mma3(acc[mf][nf], ah[mf], al[mf],
                         bh[nf >> 1][(nf & 1) * 2], bh[nf >> 1][(nf & 1) * 2 + 1],
                         bl[nf >> 1][(nf & 1) * 2], bl[nf >> 1][(nf & 1) * 2 + 1]);
        }
        __syncthreads();
    }

    const float sc = (mat == 0) ? SCALE : 1.0f;
    __nv_bfloat16* dsth = (mat == 0) ? g_qh : (mat == 1) ? g_kh : g_vh;
    __nv_bfloat16* dstl = (mat == 0) ? g_ql : (mat == 1) ? g_kl : g_vl;
    const int r0 = lane >> 2;
    const int c0 = (lane & 3) * 2;
#pragma unroll
    for (int mf = 0; mf < 4; ++mf) {
#pragma unroll
        for (int nf = 0; nf < 4; ++nf) {
            int row = m0 + wm * 64 + mf * 16 + r0;
            int col = wn * 32 + nf * 8 + c0;
            float d0 = acc[mf][nf][0] * sc, d1 = acc[mf][nf][1] * sc;
            float d2 = acc[mf][nf][2] * sc, d3 = acc[mf][nf][3] * sc;
            uint32_t h0, l0, h1, l1;
            split_pair(d0, d1, h0, l0);
            split_pair(d2, d3, h1, l1);
            *reinterpret_cast<uint32_t*>(&dsth[(size_t)row * HN + col])       = h0;
            *reinterpret_cast<uint32_t*>(&dstl[(size_t)row * HN + col])       = l0;
            *reinterpret_cast<uint32_t*>(&dsth[(size_t)(row + 8) * HN + col]) = h1;
            *reinterpret_cast<uint32_t*>(&dstl[(size_t)(row + 8) * HN + col]) = l1;
        }
    }
}

// ===========================================================================
// Kernel 2: chunkkv via mma (unchanged)
// ===========================================================================
__global__ __launch_bounds__(256) void chunkkv_mma()
{
    __shared__ __align__(16) char KHI[8192], KLO[8192], VHI[8192], VLO[8192];
    __shared__ float gp[132];

    const int c = blockIdx.x;
    const int b = blockIdx.y;
    const size_t rowbase = (size_t)(b * TN + c * LN);
    const __nv_bfloat16* __restrict__ khp = g_kh + rowbase * HN;
    const __nv_bfloat16* __restrict__ klp = g_kl + rowbase * HN;
    const __nv_bfloat16* __restrict__ vhp = g_vh + rowbase * HN;
    const __nv_bfloat16* __restrict__ vlp = g_vl + rowbase * HN;
    float* __restrict__ ap = g_A + (size_t)(b * NCN + c) * HN * HN;

    const int tid  = threadIdx.x;
    const int wid  = tid >> 5;
    const int lane = tid & 31;
    const int wm   = wid & 1;
    const int wn   = wid >> 1;

    if (tid < 132) gp[tid] = powf(GAMMA, (float)tid);
    const uint32_t skh = smem_u32(KHI), skl = smem_u32(KLO);
    const uint32_t svh = smem_u32(VHI), svl = smem_u32(VLO);
    __syncthreads();

    float acc[4][4][4];
#pragma unroll
    for (int a = 0; a < 4; ++a)
#pragma unroll
        for (int e = 0; e < 4; ++e)
#pragma unroll
            for (int f = 0; f < 4; ++f) acc[a][e][f] = 0.0f;

    for (int jt = 0; jt < 4; ++jt) {
        __syncthreads();
#pragma unroll
        for (int r = 0; r < 2; ++r) {
            int id  = tid + 256 * r;
            int row = id >> 4;
            int ch  = id & 15;
            int j   = jt * 32 + row;
            float w = gp[LN - j];
            uint4 dh = *reinterpret_cast<const uint4*>(&khp[(size_t)j * HN + ch * 8]);
            uint4 dl = *reinterpret_cast<const uint4*>(&klp[(size_t)j * HN + ch * 8]);
            const uint32_t* hw = &dh.x;
            const uint32_t* lw = &dl.x;
            uint4 vh4, vl4;
            uint32_t* ph = &vh4.x;
            uint32_t* pl = &vl4.x;
#pragma unroll
            for (int q = 0; q < 4; ++q) {
                float f0 = bf2sum(hw[q], lw[q], 0) * w;
                float f1 = bf2sum(hw[q], lw[q], 1) * w;
                split_pair(f0, f1, ph[q], pl[q]);
            }
            uint32_t dst = (uint32_t)(row * 256 + ((ch ^ (row & 7)) * 16));
            *reinterpret_cast<uint4*>(KHI + dst) = vh4;
            *reinterpret_cast<uint4*>(KLO + dst) = vl4;
        }
#pragma unroll
        for (int r = 0; r < 2; ++r) {
            int id  = tid + 256 * r;
            int row = id >> 4;
            int ch  = id & 15;
            int j   = jt * 32 + row;
            uint4 dh = *reinterpret_cast<const uint4*>(&vhp[(size_t)j * HN + ch * 8]);
            uint4 dl = *reinterpret_cast<const uint4*>(&vlp[(size_t)j * HN + ch * 8]);
            uint32_t dst = (uint32_t)(row * 256 + ((ch ^ (row & 7)) * 16));
            *reinterpret_cast<uint4*>(VHI + dst) = dh;
            *reinterpret_cast<uint4*>(VLO + dst) = dl;
        }
        __syncthreads();

#pragma unroll
        for (int kk = 0; kk < 2; ++kk) {
            uint32_t ah[4][4], al[4][4];
            const int arow = kk * 16 + (lane & 7) + ((lane >> 4) & 1) * 8;
#pragma unroll
            for (int mf = 0; mf < 4; ++mf) {
                int ach = wm * 8 + mf * 2 + ((lane >> 3) & 1);
                uint32_t so = (uint32_t)(arow * 256 + ((ach ^ (arow & 7)) * 16));
                ldm_x4_t(ah[mf], skh + so);
                ldm_x4_t(al[mf], skl + so);
            }
            uint32_t bh[2][4], bl[2][4];
            const int brow = kk * 16 + (lane & 7) + ((lane >> 3) & 1) * 8;
#pragma unroll
            for (int nf2 = 0; nf2 < 2; ++nf2) {
                int bch = wn * 4 + nf2 * 2 + ((lane >> 4) & 1);
                uint32_t so = (uint32_t)(brow * 256 + ((bch ^ (brow & 7)) * 16));
                ldm_x4_t(bh[nf2], svh + so);
                ldm_x4_t(bl[nf2], svl + so);
            }
#pragma unroll
            for (int mf = 0; mf < 4; ++mf)
#pragma unroll
                for (int nf = 0; nf < 4; ++nf)
                    mma3(acc[mf][nf], ah[mf], al[mf],
                         bh[nf >> 1][(nf & 1) * 2], bh[nf >> 1][(nf & 1) * 2 + 1],
                         bl[nf >> 1][(nf & 1) * 2], bl[nf >> 1][(nf & 1) * 2 + 1]);
        }
    }

    const int r0 = lane >> 2;
    const int c0 = (lane & 3) * 2;
#pragma unroll
    for (int mf = 0; mf < 4; ++mf)
#pragma unroll
        for (int nf = 0; nf < 4; ++nf) {
            int row = wm * 64 + mf * 16 + r0;
            int col = wn * 32 + nf * 8 + c0;
            float2 v0 = {acc[mf][nf][0], acc[mf][nf][1]};
            float2 v1 = {acc[mf][nf][2], acc[mf][nf][3]};
            *reinterpret_cast<float2*>(&ap[(size_t)row * HN + col])       = v0;
            *reinterpret_cast<float2*>(&ap[(size_t)(row + 8) * HN + col]) = v1;
        }
}

// ===========================================================================
// Kernel 3: prefix scan with batched MLP loads (latency fix).
// ===========================================================================
__global__ void scan_kernel()
{
    int idx = blockIdx.x * blockDim.x + threadIdx.x;
    if (idx >= BN * HN * HN) return;
    int b = idx / (HN * HN);
    int e = idx % (HN * HN);
    const float gL = powf(GAMMA, (float)LN);
    const size_t base = (size_t)b * NCN * HN * HN + e;

    // batched independent loads: full MLP, no serial latency chain
    float a[NCN];
#pragma unroll
    for (int c = 0; c < NCN; ++c)
        a[c] = g_A[base + (size_t)c * HN * HN];

    float S = 0.0f;
#pragma unroll
    for (int c = 0; c < NCN; ++c) {
        size_t off = base + (size_t)c * HN * HN;
        __nv_bfloat16 hi = __float2bfloat16_rn(S);
        g_Sh[off] = hi;
        g_Sl[off] = __float2bfloat16_rn(S - __bfloat162float(hi));
        S = fmaf(S, gL, a[c]);
    }
}

// ===========================================================================
// Kernel 4: out via mma.  Phases 1 (P=QK^T) and 2b (O=QS) FUSED.
// ===========================================================================
#define OP_HI 0
#define OP_LO 32768
#define OSA   65536
#define OSB   81920
#define OSC   98304
#define OUT_SMEM 114688

__global__ __launch_bounds__(256) void out_mma(float* __restrict__ out)
{
    extern __shared__ char sm[];
    __shared__ float gp[128];
    const uint32_t sb = smem_u32(sm);

    const int c = blockIdx.x;
    const int b = blockIdx.y;
    const size_t rowbase = (size_t)(b * TN + c * LN);
    const __nv_bfloat16* __restrict__ qh = g_qh + rowbase * HN;
    const __nv_bfloat16* __restrict__ ql = g_ql + rowbase * HN;
    const __nv_bfloat16* __restrict__ kh = g_kh + rowbase * HN;
    const __nv_bfloat16* __restrict__ kl = g_kl + rowbase * HN;
    const __nv_bfloat16* __restrict__ vh = g_vh + rowbase * HN;
    const __nv_bfloat16* __restrict__ vl = g_vl + rowbase * HN;
    const __nv_bfloat16* __restrict__ Sh = g_Sh + (size_t)(b * NCN + c) * HN * HN;
    const __nv_bfloat16* __restrict__ Sl = g_Sl + (size_t)(b * NCN + c) * HN * HN;

    const int tid  = threadIdx.x;
    const int wid  = tid >> 5;
    const int lane = tid & 31;
    const int wm   = wid & 1;
    const int wn   = wid >> 1;

    if (tid < 128) gp[tid] = powf(GAMMA, (float)tid);
    __syncthreads();

    auto copy128x32 = [&](int dstOff, const __nv_bfloat16* src, int h0) {
#pragma unroll
        for (int r = 0; r < 2; ++r) {
            int id  = tid + 256 * r;
            int row = id >> 2;
            int ch  = id & 3;
            uint4 d = *reinterpret_cast<const uint4*>(&src[(size_t)row * HN + h0 + ch * 8]);
            *reinterpret_cast<uint4*>(sm + dstOff + row * 64 +
                                      ((ch ^ ((row >> 1) & 3)) * 16)) = d;
        }
    };
    auto copy32x128 = [&](int dstOff, const __nv_bfloat16* src) {
#pragma unroll
        for (int r = 0; r < 2; ++r) {
            int id  = tid + 256 * r;
            int row = id >> 4;
            int ch  = id & 15;
            uint4 d = *reinterpret_cast<const uint4*>(&src[(size_t)row * HN + ch * 8]);
            *reinterpret_cast<uint4*>(sm + dstOff + row * 256 +
                                      ((ch ^ (row & 7)) * 16)) = d;
        }
    };

    // ---------------- fused phase 1 + 2b: P = Q K^T, O = Q S ---------------
    float pAcc[4][4][4], oAcc[4][4][4];
#pragma unroll
    for (int a = 0; a < 4; ++a)
#pragma unroll
        for (int e = 0; e < 4; ++e)
#pragma unroll
            for (int f = 0; f < 4; ++f) { pAcc[a][e][f] = 0.0f; oAcc[a][e][f] = 0.0f; }

    const bool p1skip = (wm == 0 && wn >= 2);   // upper triangle, all-masked
    for (int ks = 0; ks < 4; ++ks) {
        __syncthreads();
        copy128x32(OSA,        qh, ks * 32);
        copy128x32(OSA + 8192, ql, ks * 32);
        copy128x32(OSB,        kh, ks * 32);
        copy128x32(OSB + 8192, kl, ks * 32);
        copy32x128(OSC,        Sh + (size_t)ks * 32 * HN);
        copy32x128(OSC + 8192, Sl + (size_t)ks * 32 * HN);
        __syncthreads();
#pragma unroll
        for (int kk = 0; kk < 2; ++kk) {
            // shared A fragments (Q)
            uint32_t ah[4][4], al[4][4];
            const int arow = lane & 15;
            const int ach  = kk * 2 + (lane >> 4);
#pragma unroll
            for (int mf = 0; mf < 4; ++mf) {
                int row = wm * 64 + mf * 16 + arow;
                uint32_t so = (uint32_t)(row * 64 + ((ach ^ ((row >> 1) & 3)) * 16));
                ldm_x4(ah[mf], sb + OSA + so);
                ldm_x4(al[mf], sb + OSA + 8192 + so);
            }
            // phase 1 B fragments (K, normal ldm from [j][h])
            if (!p1skip) {
                uint32_t bh[2][4], bl[2][4];
                const int brow = (lane & 7) + ((lane >> 4) & 1) * 8;
                const int bch  = kk * 2 + ((lane >> 3) & 1);
#pragma unroll
                for (int nf2 = 0; nf2 < 2; ++nf2) {
                    int row = wn * 32 + nf2 * 16 + brow;
                    uint32_t so = (uint32_t)(row * 64 + ((bch ^ ((row >> 1) & 3)) * 16));
                    ldm_x4(bh[nf2], sb + OSB + so);
                    ldm_x4(bl[nf2], sb + OSB + 8192 + so);
                }
#pragma unroll
                for (int mf = 0; mf < 4; ++mf)
#pragma unroll
                    for (int nf = 0; nf < 4; ++nf)
                        mma3(pAcc[mf][nf], ah[mf], al[mf],
                             bh[nf >> 1][(nf & 1) * 2], bh[nf >> 1][(nf & 1) * 2 + 1],
                             bl[nf >> 1][(nf & 1) * 2], bl[nf >> 1][(nf & 1) * 2 + 1]);
            }
            // phase 2b B fragments (S, trans ldm from [hk][hv])
            {
                uint32_t bh[2][4], bl[2][4];
                const int brow = kk * 16 + (lane & 7) + ((lane >> 3) & 1) * 8;
#pragma unroll
                for (int nf2 = 0; nf2 < 2; ++nf2) {
                    int bch = wn * 4 + nf2 * 2 + ((lane >> 4) & 1);
                    uint32_t so = (uint32_t)(brow * 256 + ((bch ^ (brow & 7)) * 16));
                    ldm_x4_t(bh[nf2], sb + OSC + so);
                    ldm_x4_t(bl[nf2], sb + OSC + 8192 + so);
                }
#pragma unroll
                for (int mf = 0; mf < 4; ++mf)
#pragma unroll
                    for (int nf = 0; nf < 4; ++nf)
                        mma3(oAcc[mf][nf], ah[mf], al[mf],
                             bh[nf >> 1][(nf & 1) * 2], bh[nf >> 1][(nf & 1) * 2 + 1],
                             bl[nf >> 1][(nf & 1) * 2], bl[nf >> 1][(nf & 1) * 2 + 1]);
            }
        }
    }

    // ---------------- mask + split + store P to smem; scale O --------------
    {
        const int r0 = lane >> 2;
        const int c0 = (lane & 3) * 2;
#pragma unroll
        for (int mf = 0; mf < 4; ++mf) {
            int i0 = wm * 64 + mf * 16 + r0;
            int i1 = i0 + 8;
            float g0 = gp[i0], g1 = gp[i1];
#pragma unroll
            for (int nf = 0; nf < 4; ++nf) {
                int j0 = wn * 32 + nf * 8 + c0;
                int j1 = j0 + 1;
                float d0 = (i0 >= j0) ? pAcc[mf][nf][0] * gp[i0 - j0] : 0.0f;
                float d1 = (i0 >= j1) ? pAcc[mf][nf][1] * gp[i0 - j1] : 0.0f;
                float d2 = (i1 >= j0) ? pAcc[mf][nf][2] * gp[i1 - j0] : 0.0f;
                float d3 = (i1 >= j1) ? pAcc[mf][nf][3] * gp[i1 - j1] : 0.0f;
                uint32_t h0, l0, h1, l1;
                split_pair(d0, d1, h0, l0);
                split_pair(d2, d3, h1, l1);
                uint32_t a0 = (uint32_t)(i0 * 256 + (((j0 >> 3) ^ (i0 & 7)) * 16) + (j0 & 7) * 2);
                uint32_t a1 = (uint32_t)(i1 * 256 + (((j0 >> 3) ^ (i1 & 7)) * 16) + (j0 & 7) * 2);
                *reinterpret_cast<uint32_t*>(sm + OP_HI + a0) = h0;
                *reinterpret_cast<uint32_t*>(sm + OP_LO + a0) = l0;
                *reinterpret_cast<uint32_t*>(sm + OP_HI + a1) = h1;
                *reinterpret_cast<uint32_t*>(sm + OP_LO + a1) = l1;
                // scale O by gamma^i while registers are hot
                oAcc[mf][nf][0] *= g0;
                oAcc[mf][nf][1] *= g0;
                oAcc[mf][nf][2] *= g1;
                oAcc[mf][nf][3] *= g1;
            }
        }
    }

    // ---------------- phase 2a: O += P @ V ---------------------------------
    for (int jt = 0; jt < 4; ++jt) {
        __syncthreads();
        copy32x128(OSB,        vh + (size_t)jt * 32 * HN);
        copy32x128(OSB + 8192, vl + (size_t)jt * 32 * HN);
        __syncthreads();
        if (wm == 0 && jt >= 2) continue;
#pragma unroll
        for (int kk = 0; kk < 2; ++kk) {
            const int ks = jt * 2 + kk;
            uint32_t ah[4][4], al[4][4];
            const int arow = lane & 15;
            const int ach  = ks * 2 + (lane >> 4);
#pragma unroll
            for (int mf = 0; mf < 4; ++mf) {
                int row = wm * 64 + mf * 16 + arow;
                uint32_t so = (uint32_t)(row * 256 + ((ach ^ (row & 7)) * 16));
                ldm_x4(ah[mf], sb + OP_HI + so);
                ldm_x4(al[mf], sb + OP_LO + so);
            }
            uint32_t bh[2][4], bl[2][4];
            const int brow = kk * 16 + (lane & 7) + ((lane >> 3) & 1) * 8;
#pragma unroll
            for (int nf2 = 0; nf2 < 2; ++nf2) {
                int bch = wn * 4 + nf2 * 2 + ((lane >> 4) & 1);
                uint32_t so = (uint32_t)(brow * 256 + ((bch ^ (brow & 7)) * 16));
                ldm_x4_t(bh[nf2], sb + OSB + so);
                ldm_x4_t(bl[nf2], sb + OSB + 8192 + so);
            }
#pragma unroll
            for (int mf = 0; mf < 4; ++mf)
#pragma unroll
                for (int nf = 0; nf < 4; ++nf)
                    mma3(oAcc[mf][nf], ah[mf], al[mf],
                         bh[nf >> 1][(nf & 1) * 2], bh[nf >> 1][(nf & 1) * 2 + 1],
                         bl[nf >> 1][(nf & 1) * 2], bl[nf >> 1][(nf & 1) * 2 + 1]);
        }
    }

    // ---------------- store O ----------------------------------------------
    {
        const int r0 = lane >> 2;
        const int c0 = (lane & 3) * 2;
#pragma unroll
        for (int mf = 0; mf < 4; ++mf)
#pragma unroll
            for (int nf = 0; nf < 4; ++nf) {
                size_t row = rowbase + wm * 64 + mf * 16 + r0;
                int col = wn * 32 + nf * 8 + c0;
                float2 v0 = {oAcc[mf][nf][0], oAcc[mf][nf][1]};
                float2 v1 = {oAcc[mf][nf][2], oAcc[mf][nf][3]};
                *reinterpret_cast<float2*>(&out[row * HN + col])       = v0;
                *reinterpret_cast<float2*>(&out[(row + 8) * HN + col]) = v1;
            }
    }
}

// ===========================================================================
extern "C" void kernel_launch(void* const* d_in, const int* in_sizes, int n_in,
                              void* d_out, int out_size)
{
    const float* x  = (const float*)d_in[0];
    const float* Wq = (const float*)d_in[1];
    const float* Wk = (const float*)d_in[2];
    const float* Wv = (const float*)d_in[3];
    float* out = (float*)d_out;

    cudaFuncSetAttribute(proj_mma_kernel, cudaFuncAttributeMaxDynamicSharedMemorySize,
                         2 * BUF_SZ);
    cudaFuncSetAttribute(out_mma, cudaFuncAttributeMaxDynamicSharedMemorySize,
                         OUT_SMEM);

    wprep_kernel<<<dim3(CN, 3), HN>>>(Wq, Wk, Wv);
    proj_mma_kernel<<<dim3(3, MN / 128), 256, 2 * BUF_SZ>>>(x);
    chunkkv_mma<<<dim3(NCN, BN), 256>>>();
    scan_kernel<<<(BN * HN * HN + 255) / 256, 256>>>();
    out_mma<<<dim3(NCN, BN), 256, OUT_SMEM>>>(out);
}